// round 2
// baseline (speedup 1.0000x reference)
#include <cuda_runtime.h>
#include <math.h>
#include <stddef.h>

#define Bb   32
#define Hh   56
#define Ww   56
#define Cc   192
#define WS   7
#define SS   3
#define NHd  6
#define Nn   49
#define HD   32
#define NWIN 64
#define NWTOT 2048
#define TOK  100352
#define HID  768
#define SCALE 0.17677669529663687f  /* 32^-0.5 */

// ---------------- scratch (device globals; no allocations) ----------------
__device__ float g_xw  [(size_t)NWTOT * Nn * Cc];      // LN1+shift+partition out; reused as proj-GEMM out
__device__ float g_qkv [(size_t)NWTOT * Nn * 3 * Cc];  // qkv
__device__ float g_attn[(size_t)NWTOT * Nn * Cc];      // attention out (window order)
__device__ float g_h   [(size_t)TOK * Cc];             // h = x + attn_proj  (token order)
__device__ float g_ln2 [(size_t)TOK * Cc];             // LN2(h)
__device__ float g_act [(size_t)TOK * HID];            // gelu(fc1)

// ---------------- block reduce over 192 threads (6 warps) ----------------
__device__ __forceinline__ float blk_sum192(float v, float* red) {
    #pragma unroll
    for (int o = 16; o; o >>= 1) v += __shfl_xor_sync(0xffffffffu, v, o);
    if ((threadIdx.x & 31) == 0) red[threadIdx.x >> 5] = v;
    __syncthreads();
    float t = red[0] + red[1] + red[2] + red[3] + red[4] + red[5];
    __syncthreads();
    return t;
}

// ---------------- LN1 + roll(-3,-3) + window partition ----------------
// one block per DST window-token, 192 threads (one per channel)
__global__ void ln1_shift_part(const float* __restrict__ x,
                               const float* __restrict__ g,
                               const float* __restrict__ b) {
    __shared__ float red[6];
    int t  = blockIdx.x;              // window-token index
    int wi = t / Nn, n = t - wi * Nn;
    int bi = wi >> 6, wl = wi & 63;
    int wr = wl >> 3, wc = wl & 7;
    int r  = n / 7,  c2 = n - r * 7;
    int hsrc = (wr * 7 + r + SS) % Hh;
    int wsrc = (wc * 7 + c2 + SS) % Ww;
    const float* row = x + ((size_t)bi * (Hh * Ww) + hsrc * Ww + wsrc) * Cc;
    int c = threadIdx.x;
    float v = row[c];
    float mean = blk_sum192(v, red) * (1.0f / Cc);
    float d = v - mean;
    float var = blk_sum192(d * d, red) * (1.0f / Cc);
    g_xw[(size_t)t * Cc + c] = d * rsqrtf(var + 1e-5f) * g[c] + b[c];
}

// ---------------- LN2 (token order, identity mapping) ----------------
__global__ void ln2_k(const float* __restrict__ g, const float* __restrict__ b) {
    __shared__ float red[6];
    int t = blockIdx.x, c = threadIdx.x;
    float v = g_h[(size_t)t * Cc + c];
    float mean = blk_sum192(v, red) * (1.0f / Cc);
    float d = v - mean;
    float var = blk_sum192(d * d, red) * (1.0f / Cc);
    g_ln2[(size_t)t * Cc + c] = d * rsqrtf(var + 1e-5f) * g[c] + b[c];
}

// ---------------- generic fp32 tiled GEMM: C = A[M,K] * W[Nc,K]^T + bias ----------------
// EPI: 0 = +bias, 1 = +bias then exact GELU, 2 = +bias + resid
template <int EPI>
__global__ void __launch_bounds__(256)
gemm_k(const float* __restrict__ A, const float* __restrict__ Wm,
       const float* __restrict__ bias, const float* __restrict__ resid,
       float* __restrict__ Cm, int M, int Nc, int K) {
    __shared__ float As[16][64];
    __shared__ float Bs[16][64];
    const int tid = threadIdx.x;
    const int tx = tid & 15, ty = tid >> 4;
    const int m0 = blockIdx.y << 6, n0 = blockIdx.x << 6;
    const int lrow = tid >> 2;
    const int lseg = (tid & 3) << 2;

    float acc[4][4];
    #pragma unroll
    for (int i = 0; i < 4; i++)
        #pragma unroll
        for (int j = 0; j < 4; j++) acc[i][j] = 0.0f;

    const float* Ap = A  + (size_t)(m0 + lrow) * K + lseg;
    const float* Wp = Wm + (size_t)(n0 + lrow) * K + lseg;

    for (int k0 = 0; k0 < K; k0 += 16) {
        float4 a = *(const float4*)(Ap + k0);
        float4 w = *(const float4*)(Wp + k0);
        As[lseg + 0][lrow] = a.x; As[lseg + 1][lrow] = a.y;
        As[lseg + 2][lrow] = a.z; As[lseg + 3][lrow] = a.w;
        Bs[lseg + 0][lrow] = w.x; Bs[lseg + 1][lrow] = w.y;
        Bs[lseg + 2][lrow] = w.z; Bs[lseg + 3][lrow] = w.w;
        __syncthreads();
        #pragma unroll
        for (int kk = 0; kk < 16; kk++) {
            float4 av = *(const float4*)(&As[kk][ty << 2]);
            float4 bv = *(const float4*)(&Bs[kk][tx << 2]);
            float af[4] = {av.x, av.y, av.z, av.w};
            float bf[4] = {bv.x, bv.y, bv.z, bv.w};
            #pragma unroll
            for (int i = 0; i < 4; i++)
                #pragma unroll
                for (int j = 0; j < 4; j++) acc[i][j] += af[i] * bf[j];
        }
        __syncthreads();
    }

    #pragma unroll
    for (int i = 0; i < 4; i++) {
        int m = m0 + (ty << 2) + i;
        #pragma unroll
        for (int j = 0; j < 4; j++) {
            int n = n0 + (tx << 2) + j;
            float cv = acc[i][j] + bias[n];
            if (EPI == 1) cv = 0.5f * cv * (1.0f + erff(cv * 0.70710678118654752f));
            if (EPI == 2) cv += resid[(size_t)m * Nc + n];
            Cm[(size_t)m * Nc + n] = cv;
        }
    }
}

// ---------------- fused window attention: one block per (window, head) ----------------
__global__ void __launch_bounds__(256)
attn_k(const float* __restrict__ rpb) {
    __shared__ float sq[Nn][HD + 1];
    __shared__ float sk[Nn][HD + 1];
    __shared__ float sv[Nn][HD + 1];
    __shared__ float p[Nn][Nn];
    __shared__ int   rg[Nn];

    const int wi = blockIdx.x;   // 0..2047
    const int nh = blockIdx.y;   // 0..5
    const int tid = threadIdx.x;

    // load q,k,v tiles for this head
    for (int i = tid; i < Nn * HD; i += 256) {
        int n = i >> 5, d = i & 31;
        const float* base = g_qkv + (size_t)(wi * Nn + n) * (3 * Cc) + nh * HD + d;
        sq[n][d] = base[0];
        sk[n][d] = base[Cc];
        sv[n][d] = base[2 * Cc];
    }
    // region ids for shift mask (computed analytically)
    // axis regions: [0, H-WS)=[0,49) -> 0, [H-WS, H-SS)=[49,53) -> 1, [53,56) -> 2
    if (tid < Nn) {
        int wl = wi & 63;
        int wr = wl >> 3, wc = wl & 7;
        int r = tid / 7, c2 = tid - (tid / 7) * 7;
        int hs = wr * 7 + r, ws = wc * 7 + c2;
        int rh = hs < (Hh - WS) ? 0 : (hs < (Hh - SS) ? 1 : 2);
        int rw = ws < (Ww - WS) ? 0 : (ws < (Ww - SS) ? 1 : 2);
        rg[tid] = rh * 3 + rw;
    }
    __syncthreads();

    // logits + bias + mask
    for (int i = tid; i < Nn * Nn; i += 256) {
        int n = i / Nn, m = i - n * Nn;
        float acc = 0.0f;
        #pragma unroll 8
        for (int d = 0; d < HD; d++) acc += sq[n][d] * sk[m][d];
        int r1 = n / 7, c1 = n - r1 * 7;
        int r2 = m / 7, c2 = m - r2 * 7;
        int idx = (r1 - r2 + 6) * 13 + (c1 - c2 + 6);
        float bias = rpb[idx * NHd + nh];
        float mask = (rg[n] == rg[m]) ? 0.0f : -100.0f;
        p[n][m] = acc * SCALE + bias + mask;
    }
    __syncthreads();

    // softmax: one warp per row
    int warp = tid >> 5, lane = tid & 31;
    for (int n = warp; n < Nn; n += 8) {
        float mx = -1e30f;
        for (int m = lane; m < Nn; m += 32) mx = fmaxf(mx, p[n][m]);
        #pragma unroll
        for (int o = 16; o; o >>= 1) mx = fmaxf(mx, __shfl_xor_sync(0xffffffffu, mx, o));
        float sm = 0.0f;
        for (int m = lane; m < Nn; m += 32) {
            float e = __expf(p[n][m] - mx);
            p[n][m] = e;
            sm += e;
        }
        #pragma unroll
        for (int o = 16; o; o >>= 1) sm += __shfl_xor_sync(0xffffffffu, sm, o);
        float inv = 1.0f / sm;
        for (int m = lane; m < Nn; m += 32) p[n][m] *= inv;
    }
    __syncthreads();

    // out = p @ v
    for (int i = tid; i < Nn * HD; i += 256) {
        int n = i >> 5, d = i & 31;
        float acc = 0.0f;
        #pragma unroll 7
        for (int m = 0; m < Nn; m++) acc += p[n][m] * sv[m][d];
        g_attn[(size_t)(wi * Nn + n) * Cc + nh * HD + d] = acc;
    }
}

// ---------------- window-reverse + roll(+3,+3) + residual: h = x + scatter(proj_out) ----------------
__global__ void scatter_resid(const float* __restrict__ x) {
    int idx = blockIdx.x * 256 + threadIdx.x;   // over TOK*Cc, exact multiple
    int c = idx % Cc;
    int t = idx / Cc;
    int wi = t / Nn, n = t - wi * Nn;
    int bi = wi >> 6, wl = wi & 63;
    int wr = wl >> 3, wc = wl & 7;
    int r = n / 7, c2 = n - r * 7;
    int hd = (wr * 7 + r + SS) % Hh;
    int wd = (wc * 7 + c2 + SS) % Ww;
    size_t dst = ((size_t)bi * (Hh * Ww) + hd * Ww + wd) * Cc + c;
    g_h[dst] = x[dst] + g_xw[(size_t)idx];
}

// ---------------- host ----------------
extern "C" void kernel_launch(void* const* d_in, const int* in_sizes, int n_in,
                              void* d_out, int out_size) {
    const float* x     = (const float*)d_in[0];
    const float* n1g   = (const float*)d_in[1];
    const float* n1b   = (const float*)d_in[2];
    const float* qkvw  = (const float*)d_in[3];
    const float* qkvb  = (const float*)d_in[4];
    const float* projw = (const float*)d_in[5];
    const float* projb = (const float*)d_in[6];
    const float* rpb   = (const float*)d_in[7];
    const float* n2g   = (const float*)d_in[8];
    const float* n2b   = (const float*)d_in[9];
    const float* fc1w  = (const float*)d_in[10];
    const float* fc1b  = (const float*)d_in[11];
    const float* fc2w  = (const float*)d_in[12];
    const float* fc2b  = (const float*)d_in[13];
    float* out = (float*)d_out;

    static float *p_xw = nullptr, *p_qkv = nullptr, *p_attn = nullptr,
                 *p_h = nullptr, *p_ln2 = nullptr, *p_act = nullptr;
    if (!p_xw) {
        cudaGetSymbolAddress((void**)&p_xw,  g_xw);
        cudaGetSymbolAddress((void**)&p_qkv, g_qkv);
        cudaGetSymbolAddress((void**)&p_attn,g_attn);
        cudaGetSymbolAddress((void**)&p_h,   g_h);
        cudaGetSymbolAddress((void**)&p_ln2, g_ln2);
        cudaGetSymbolAddress((void**)&p_act, g_act);
    }

    // 1) LN1 + roll + window partition
    ln1_shift_part<<<TOK, 192>>>(x, n1g, n1b);
    // 2) QKV GEMM  [TOK,576] = xw @ qkv_w^T + b
    gemm_k<0><<<dim3((3 * Cc) / 64, TOK / 64), 256>>>(p_xw, qkvw, qkvb, nullptr, p_qkv, TOK, 3 * Cc, Cc);
    // 3) window attention (bias + shift-mask + softmax + PV)
    attn_k<<<dim3(NWTOT, NHd), 256>>>(rpb);
    // 4) proj GEMM -> window-order tmp (reuse g_xw)
    gemm_k<0><<<dim3(Cc / 64, TOK / 64), 256>>>(p_attn, projw, projb, nullptr, p_xw, TOK, Cc, Cc);
    // 5) window reverse + roll back + residual -> h
    scatter_resid<<<(TOK * Cc) / 256, 256>>>(x);
    // 6) LN2
    ln2_k<<<TOK, 192>>>(n2g, n2b);
    // 7) FC1 + GELU
    gemm_k<1><<<dim3(HID / 64, TOK / 64), 256>>>(p_ln2, fc1w, fc1b, nullptr, p_act, TOK, HID, Cc);
    // 8) FC2 + residual -> out
    gemm_k<2><<<dim3(Cc / 64, TOK / 64), 256>>>(p_act, fc2w, fc2b, p_h, out, TOK, Cc, HID);
}

// round 3
// speedup vs baseline: 1.5354x; 1.5354x over previous
#include <cuda_runtime.h>
#include <math.h>
#include <stddef.h>
#include <stdint.h>

#define Bb   32
#define Hh   56
#define Ww   56
#define Cc   192
#define WS   7
#define SS   3
#define NHd  6
#define Nn   49
#define HD   32
#define NWTOT 2048
#define TOK  100352
#define HID  768
#define SCALE 0.17677669529663687f  /* 32^-0.5 */

// ---------------- scratch (device globals; no allocations) ----------------
__device__ float g_xw  [(size_t)TOK * Cc];       // LN1+shift+partition out (window order)
__device__ float g_qkv [(size_t)TOK * 3 * Cc];   // qkv (window order)
__device__ float g_attn[(size_t)TOK * Cc];       // attention out (window order)
__device__ float g_h   [(size_t)TOK * Cc];       // h = x + attn_proj  (token order)
__device__ float g_ln2 [(size_t)TOK * Cc];       // LN2(h)
__device__ float g_act [(size_t)TOK * HID];      // gelu(fc1)

// ---------------- block reduce over 192 threads (6 warps) ----------------
__device__ __forceinline__ float blk_sum192(float v, float* red) {
    #pragma unroll
    for (int o = 16; o; o >>= 1) v += __shfl_xor_sync(0xffffffffu, v, o);
    if ((threadIdx.x & 31) == 0) red[threadIdx.x >> 5] = v;
    __syncthreads();
    float t = red[0] + red[1] + red[2] + red[3] + red[4] + red[5];
    __syncthreads();
    return t;
}

// ---------------- LN1 + roll(-3,-3) + window partition ----------------
__global__ void ln1_shift_part(const float* __restrict__ x,
                               const float* __restrict__ g,
                               const float* __restrict__ b) {
    __shared__ float red[6];
    int t  = blockIdx.x;              // window-token index
    int wi = t / Nn, n = t - wi * Nn;
    int bi = wi >> 6, wl = wi & 63;
    int wr = wl >> 3, wc = wl & 7;
    int r  = n / 7,  c2 = n - r * 7;
    int hsrc = (wr * 7 + r + SS) % Hh;
    int wsrc = (wc * 7 + c2 + SS) % Ww;
    const float* row = x + ((size_t)bi * (Hh * Ww) + hsrc * Ww + wsrc) * Cc;
    int c = threadIdx.x;
    float v = row[c];
    float mean = blk_sum192(v, red) * (1.0f / Cc);
    float d = v - mean;
    float var = blk_sum192(d * d, red) * (1.0f / Cc);
    g_xw[(size_t)t * Cc + c] = d * rsqrtf(var + 1e-5f) * g[c] + b[c];
}

// ---------------- LN2 (token order) ----------------
__global__ void ln2_k(const float* __restrict__ g, const float* __restrict__ b) {
    __shared__ float red[6];
    int t = blockIdx.x, c = threadIdx.x;
    float v = g_h[(size_t)t * Cc + c];
    float mean = blk_sum192(v, red) * (1.0f / Cc);
    float d = v - mean;
    float var = blk_sum192(d * d, red) * (1.0f / Cc);
    g_ln2[(size_t)t * Cc + c] = d * rsqrtf(var + 1e-5f) * g[c] + b[c];
}

// ---------------- tf32 helpers ----------------
__device__ __forceinline__ float to_tf32(float v) {
    uint32_t o;
    asm("cvt.rna.tf32.f32 %0, %1;" : "=r"(o) : "f"(v));
    return __uint_as_float(o);
}
__device__ __forceinline__ void mma_tf32(float* c, const float* a, const float* b) {
    asm volatile(
        "mma.sync.aligned.m16n8k8.row.col.f32.tf32.tf32.f32 "
        "{%0,%1,%2,%3}, {%4,%5,%6,%7}, {%8,%9}, {%0,%1,%2,%3};"
        : "+f"(c[0]), "+f"(c[1]), "+f"(c[2]), "+f"(c[3])
        : "r"(__float_as_uint(a[0])), "r"(__float_as_uint(a[1])),
          "r"(__float_as_uint(a[2])), "r"(__float_as_uint(a[3])),
          "r"(__float_as_uint(b[0])), "r"(__float_as_uint(b[1])));
}

// ---------------- tensor-core tf32 GEMM: C = A[M,K] @ W[Nc,K]^T + bias ----------------
// BM=128, BN=64, BK=32; 128 threads (4 warps, 2x2), warp tile 64x32.
// EPI: 0 = +bias            (qkv)
//      1 = +bias, GELU      (fc1)
//      2 = +bias, scatter window->token order, +resid (proj: C/resid token order)
//      3 = +bias, +resid    (fc2)
template <int EPI>
__global__ void __launch_bounds__(128)
gemm_tc(const float* __restrict__ A, const float* __restrict__ W,
        const float* __restrict__ bias, const float* __restrict__ resid,
        float* __restrict__ C, int M, int Nc, int K) {
    __shared__ float As[32][136];   // [k][m], pad 8 -> conflict-free
    __shared__ float Bs[32][72];    // [k][n], pad 8

    const int tid  = threadIdx.x;
    const int wid  = tid >> 5, lane = tid & 31;
    const int gp   = lane >> 2, tg = lane & 3;
    const int m0   = blockIdx.y << 7;
    const int n0   = blockIdx.x << 6;
    const int wm   = (wid & 1) << 6;   // 0 / 64
    const int wn   = (wid >> 1) << 5;  // 0 / 32

    float acc[4][4][4];
    #pragma unroll
    for (int i = 0; i < 4; i++)
        #pragma unroll
        for (int j = 0; j < 4; j++)
            #pragma unroll
            for (int e = 0; e < 4; e++) acc[i][j][e] = 0.0f;

    const float* Ap = A + (size_t)(m0 + tid) * K;
    const int    bn = tid & 63;          // 0..63
    const int    bh = (tid >> 6) << 4;   // 0 / 16
    const float* Wp = W + (size_t)(n0 + bn) * K + bh;

    for (int k0 = 0; k0 < K; k0 += 32) {
        // load A tile (each thread: one m-row, 8 float4 along k)
        #pragma unroll
        for (int s = 0; s < 8; s++) {
            float4 v = *(const float4*)(Ap + k0 + s * 4);
            As[s * 4 + 0][tid] = to_tf32(v.x);
            As[s * 4 + 1][tid] = to_tf32(v.y);
            As[s * 4 + 2][tid] = to_tf32(v.z);
            As[s * 4 + 3][tid] = to_tf32(v.w);
        }
        // load B tile (each thread: one n-row, 4 float4 over half the k range)
        #pragma unroll
        for (int s = 0; s < 4; s++) {
            float4 v = *(const float4*)(Wp + k0 + s * 4);
            Bs[bh + s * 4 + 0][bn] = to_tf32(v.x);
            Bs[bh + s * 4 + 1][bn] = to_tf32(v.y);
            Bs[bh + s * 4 + 2][bn] = to_tf32(v.z);
            Bs[bh + s * 4 + 3][bn] = to_tf32(v.w);
        }
        __syncthreads();

        #pragma unroll
        for (int ks = 0; ks < 4; ks++) {
            const int kb = ks << 3;
            float af[4][4];
            #pragma unroll
            for (int i = 0; i < 4; i++) {
                const int mm = wm + (i << 4) + gp;
                af[i][0] = As[kb + tg    ][mm    ];
                af[i][1] = As[kb + tg    ][mm + 8];
                af[i][2] = As[kb + tg + 4][mm    ];
                af[i][3] = As[kb + tg + 4][mm + 8];
            }
            float bf[4][2];
            #pragma unroll
            for (int j = 0; j < 4; j++) {
                const int nn = wn + (j << 3) + gp;
                bf[j][0] = Bs[kb + tg    ][nn];
                bf[j][1] = Bs[kb + tg + 4][nn];
            }
            #pragma unroll
            for (int i = 0; i < 4; i++)
                #pragma unroll
                for (int j = 0; j < 4; j++)
                    mma_tf32(acc[i][j], af[i], bf[j]);
        }
        __syncthreads();
    }

    // epilogue
    #pragma unroll
    for (int i = 0; i < 4; i++) {
        #pragma unroll
        for (int half = 0; half < 2; half++) {
            const int row = m0 + wm + (i << 4) + gp + (half << 3);
            size_t rowoff;
            if (EPI == 2) {
                // window token -> token order (window reverse + roll(+3,+3))
                int wi2 = row / Nn, nn2 = row - wi2 * Nn;
                int bi = wi2 >> 6, wl = wi2 & 63;
                int wr = wl >> 3, wc = wl & 7;
                int rr = nn2 / 7, cc = nn2 - rr * 7;
                int hd = (wr * 7 + rr + SS) % Hh;
                int wd = (wc * 7 + cc + SS) % Ww;
                rowoff = ((size_t)bi * (Hh * Ww) + hd * Ww + wd) * (size_t)Nc;
            } else {
                rowoff = (size_t)row * Nc;
            }
            #pragma unroll
            for (int j = 0; j < 4; j++) {
                const int ncol = n0 + wn + (j << 3) + (tg << 1);
                #pragma unroll
                for (int e = 0; e < 2; e++) {
                    float cv = acc[i][j][half * 2 + e] + bias[ncol + e];
                    if (EPI == 1)
                        cv = 0.5f * cv * (1.0f + erff(cv * 0.70710678118654752f));
                    if (EPI == 2 || EPI == 3)
                        cv += resid[rowoff + ncol + e];
                    C[rowoff + ncol + e] = cv;
                }
            }
        }
    }
}

// ---------------- fused window attention: one block per (window, head) ----------------
__global__ void __launch_bounds__(256)
attn_k(const float* __restrict__ rpb) {
    __shared__ float sq[Nn][HD + 1];
    __shared__ float sk[Nn][HD + 1];
    __shared__ float sv[Nn][HD + 1];
    __shared__ float p[Nn][Nn];
    __shared__ int   rg[Nn];

    const int wi = blockIdx.x;
    const int nh = blockIdx.y;
    const int tid = threadIdx.x;

    for (int i = tid; i < Nn * HD; i += 256) {
        int n = i >> 5, d = i & 31;
        const float* base = g_qkv + (size_t)(wi * Nn + n) * (3 * Cc) + nh * HD + d;
        sq[n][d] = base[0];
        sk[n][d] = base[Cc];
        sv[n][d] = base[2 * Cc];
    }
    if (tid < Nn) {
        int wl = wi & 63;
        int wr = wl >> 3, wc = wl & 7;
        int r = tid / 7, c2 = tid - (tid / 7) * 7;
        int hs = wr * 7 + r, ws = wc * 7 + c2;
        int rh = hs < (Hh - WS) ? 0 : (hs < (Hh - SS) ? 1 : 2);
        int rw = ws < (Ww - WS) ? 0 : (ws < (Ww - SS) ? 1 : 2);
        rg[tid] = rh * 3 + rw;
    }
    __syncthreads();

    for (int i = tid; i < Nn * Nn; i += 256) {
        int n = i / Nn, m = i - n * Nn;
        float acc = 0.0f;
        #pragma unroll 8
        for (int d = 0; d < HD; d++) acc += sq[n][d] * sk[m][d];
        int r1 = n / 7, c1 = n - r1 * 7;
        int r2 = m / 7, c2 = m - r2 * 7;
        int idx = (r1 - r2 + 6) * 13 + (c1 - c2 + 6);
        float bias = rpb[idx * NHd + nh];
        float mask = (rg[n] == rg[m]) ? 0.0f : -100.0f;
        p[n][m] = acc * SCALE + bias + mask;
    }
    __syncthreads();

    int warp = tid >> 5, lane = tid & 31;
    for (int n = warp; n < Nn; n += 8) {
        float mx = -1e30f;
        for (int m = lane; m < Nn; m += 32) mx = fmaxf(mx, p[n][m]);
        #pragma unroll
        for (int o = 16; o; o >>= 1) mx = fmaxf(mx, __shfl_xor_sync(0xffffffffu, mx, o));
        float sm = 0.0f;
        for (int m = lane; m < Nn; m += 32) {
            float e = __expf(p[n][m] - mx);
            p[n][m] = e;
            sm += e;
        }
        #pragma unroll
        for (int o = 16; o; o >>= 1) sm += __shfl_xor_sync(0xffffffffu, sm, o);
        float inv = 1.0f / sm;
        for (int m = lane; m < Nn; m += 32) p[n][m] *= inv;
    }
    __syncthreads();

    for (int i = tid; i < Nn * HD; i += 256) {
        int n = i >> 5, d = i & 31;
        float acc = 0.0f;
        #pragma unroll 7
        for (int m = 0; m < Nn; m++) acc += p[n][m] * sv[m][d];
        g_attn[(size_t)(wi * Nn + n) * Cc + nh * HD + d] = acc;
    }
}

// ---------------- host ----------------
extern "C" void kernel_launch(void* const* d_in, const int* in_sizes, int n_in,
                              void* d_out, int out_size) {
    const float* x     = (const float*)d_in[0];
    const float* n1g   = (const float*)d_in[1];
    const float* n1b   = (const float*)d_in[2];
    const float* qkvw  = (const float*)d_in[3];
    const float* qkvb  = (const float*)d_in[4];
    const float* projw = (const float*)d_in[5];
    const float* projb = (const float*)d_in[6];
    const float* rpb   = (const float*)d_in[7];
    const float* n2g   = (const float*)d_in[8];
    const float* n2b   = (const float*)d_in[9];
    const float* fc1w  = (const float*)d_in[10];
    const float* fc1b  = (const float*)d_in[11];
    const float* fc2w  = (const float*)d_in[12];
    const float* fc2b  = (const float*)d_in[13];
    float* out = (float*)d_out;

    static float *p_xw = nullptr, *p_qkv = nullptr, *p_attn = nullptr,
                 *p_h = nullptr, *p_ln2 = nullptr, *p_act = nullptr;
    if (!p_xw) {
        cudaGetSymbolAddress((void**)&p_xw,  g_xw);
        cudaGetSymbolAddress((void**)&p_qkv, g_qkv);
        cudaGetSymbolAddress((void**)&p_attn,g_attn);
        cudaGetSymbolAddress((void**)&p_h,   g_h);
        cudaGetSymbolAddress((void**)&p_ln2, g_ln2);
        cudaGetSymbolAddress((void**)&p_act, g_act);
    }

    // 1) LN1 + roll + window partition
    ln1_shift_part<<<TOK, 192>>>(x, n1g, n1b);
    // 2) QKV GEMM  [TOK,576]
    gemm_tc<0><<<dim3((3 * Cc) / 64, TOK / 128), 128>>>(p_xw, qkvw, qkvb, nullptr, p_qkv, TOK, 3 * Cc, Cc);
    // 3) window attention
    attn_k<<<dim3(NWTOT, NHd), 256>>>(rpb);
    // 4) proj GEMM fused with window-reverse + roll-back + residual -> h (token order)
    gemm_tc<2><<<dim3(Cc / 64, TOK / 128), 128>>>(p_attn, projw, projb, x, p_h, TOK, Cc, Cc);
    // 5) LN2
    ln2_k<<<TOK, 192>>>(n2g, n2b);
    // 6) FC1 + GELU
    gemm_tc<1><<<dim3(HID / 64, TOK / 128), 128>>>(p_ln2, fc1w, fc1b, nullptr, p_act, TOK, HID, Cc);
    // 7) FC2 + residual -> out
    gemm_tc<3><<<dim3(Cc / 64, TOK / 128), 128>>>(p_act, fc2w, fc2b, p_h, out, TOK, Cc, HID);
}

// round 4
// speedup vs baseline: 1.5600x; 1.0160x over previous
#include <cuda_runtime.h>
#include <math.h>
#include <stddef.h>
#include <stdint.h>

#define Bb   32
#define Hh   56
#define Ww   56
#define Cc   192
#define WS   7
#define SS   3
#define NHd  6
#define Nn   49
#define HD   32
#define NWTOT 2048
#define TOK  100352
#define HID  768
#define SCALE 0.17677669529663687f  /* 32^-0.5 */

// ---------------- scratch (device globals; no allocations) ----------------
__device__ float g_xw  [(size_t)TOK * Cc];       // LN1+shift+partition out (window order)
__device__ float g_qkv [(size_t)TOK * 3 * Cc];   // qkv (window order)
__device__ float g_attn[(size_t)TOK * Cc];       // attention out (window order)
__device__ float g_h   [(size_t)TOK * Cc];       // h = x + attn_proj  (token order)
__device__ float g_ln2 [(size_t)TOK * Cc];       // LN2(h)
__device__ float g_act [(size_t)TOK * HID];      // gelu(fc1)

// ---------------- block reduce over 192 threads (6 warps) ----------------
__device__ __forceinline__ float blk_sum192(float v, float* red) {
    #pragma unroll
    for (int o = 16; o; o >>= 1) v += __shfl_xor_sync(0xffffffffu, v, o);
    if ((threadIdx.x & 31) == 0) red[threadIdx.x >> 5] = v;
    __syncthreads();
    float t = red[0] + red[1] + red[2] + red[3] + red[4] + red[5];
    __syncthreads();
    return t;
}

// ---------------- LN1 + roll(-3,-3) + window partition ----------------
__global__ void ln1_shift_part(const float* __restrict__ x,
                               const float* __restrict__ g,
                               const float* __restrict__ b) {
    __shared__ float red[6];
    int t  = blockIdx.x;              // window-token index
    int wi = t / Nn, n = t - wi * Nn;
    int bi = wi >> 6, wl = wi & 63;
    int wr = wl >> 3, wc = wl & 7;
    int r  = n / 7,  c2 = n - r * 7;
    int hsrc = (wr * 7 + r + SS) % Hh;
    int wsrc = (wc * 7 + c2 + SS) % Ww;
    const float* row = x + ((size_t)bi * (Hh * Ww) + hsrc * Ww + wsrc) * Cc;
    int c = threadIdx.x;
    float v = row[c];
    float mean = blk_sum192(v, red) * (1.0f / Cc);
    float d = v - mean;
    float var = blk_sum192(d * d, red) * (1.0f / Cc);
    g_xw[(size_t)t * Cc + c] = d * rsqrtf(var + 1e-5f) * g[c] + b[c];
}

// ---------------- LN2 (token order) ----------------
__global__ void ln2_k(const float* __restrict__ g, const float* __restrict__ b) {
    __shared__ float red[6];
    int t = blockIdx.x, c = threadIdx.x;
    float v = g_h[(size_t)t * Cc + c];
    float mean = blk_sum192(v, red) * (1.0f / Cc);
    float d = v - mean;
    float var = blk_sum192(d * d, red) * (1.0f / Cc);
    g_ln2[(size_t)t * Cc + c] = d * rsqrtf(var + 1e-5f) * g[c] + b[c];
}

// ---------------- tf32 helpers ----------------
__device__ __forceinline__ float to_tf32(float v) {
    uint32_t o;
    asm("cvt.rna.tf32.f32 %0, %1;" : "=r"(o) : "f"(v));
    return __uint_as_float(o);
}
__device__ __forceinline__ void mma_tf32(float* c, const float* a, const float* b) {
    asm volatile(
        "mma.sync.aligned.m16n8k8.row.col.f32.tf32.tf32.f32 "
        "{%0,%1,%2,%3}, {%4,%5,%6,%7}, {%8,%9}, {%0,%1,%2,%3};"
        : "+f"(c[0]), "+f"(c[1]), "+f"(c[2]), "+f"(c[3])
        : "r"(__float_as_uint(a[0])), "r"(__float_as_uint(a[1])),
          "r"(__float_as_uint(a[2])), "r"(__float_as_uint(a[3])),
          "r"(__float_as_uint(b[0])), "r"(__float_as_uint(b[1])));
}

// butterfly select: q[w] = p[w ^ r], r in 0..3
__device__ __forceinline__ void rot4(const float2* p, int r, float2* q) {
    float2 a0 = (r & 1) ? p[1] : p[0];
    float2 a1 = (r & 1) ? p[0] : p[1];
    float2 a2 = (r & 1) ? p[3] : p[2];
    float2 a3 = (r & 1) ? p[2] : p[3];
    q[0] = (r & 2) ? a2 : a0;
    q[1] = (r & 2) ? a3 : a1;
    q[2] = (r & 2) ? a0 : a2;
    q[3] = (r & 2) ? a1 : a3;
}

// ---------------- tensor-core tf32 GEMM: C = A[M,K] @ W[Nc,K]^T + bias ----------------
// BM=128, BN=64, BK=32; 128 threads (4 warps, 2x2), warp tile 64x32.
// smem tiles stored in MMA-fragment order for vectorized LDS.64:
//   A: chunk(i m16-group, kb k8) = 128 floats: [half m-region][lane slot gp*4+tg] =
//      float2 (A[m][kb*8+tg], A[m][kb*8+4+tg])
//   B: chunk(j n8-group, kb) = 64 floats: [lane slot gp*4+tg] =
//      float2 (B[n][kb*8+tg], B[n][kb*8+4+tg])
// EPI: 0 = +bias  (qkv)   1 = +bias,GELU (fc1)
//      2 = +bias, scatter window->token, +resid (proj)   3 = +bias,+resid (fc2)
template <int EPI>
__global__ void __launch_bounds__(128)
gemm_tc(const float* __restrict__ A, const float* __restrict__ W,
        const float* __restrict__ bias, const float* __restrict__ resid,
        float* __restrict__ C, int M, int Nc, int K) {
    __shared__ float As[8 * 4 * 128];   // 4096 floats = 16KB
    __shared__ float Bs[8 * 4 * 64];    // 2048 floats = 8KB

    const int tid  = threadIdx.x;
    const int wid  = tid >> 5, lane = tid & 31;
    const int gp   = lane >> 2, tg = lane & 3;
    const int m0   = blockIdx.y << 7;
    const int n0   = blockIdx.x << 6;
    const int wm   = (wid & 1) << 6;   // 0 / 64
    const int wn   = (wid >> 1) << 5;  // 0 / 32

    float acc[4][4][4];
    #pragma unroll
    for (int i = 0; i < 4; i++)
        #pragma unroll
        for (int j = 0; j < 4; j++)
            #pragma unroll
            for (int e = 0; e < 4; e++) acc[i][j][e] = 0.0f;

    // A loader: thread -> row m = tid
    const float* Ap = A + (size_t)(m0 + tid) * K;
    const int aGrp  = tid >> 4;            // m16 group 0..7
    const int aHalf = (tid >> 3) & 1;
    const int aGp   = tid & 7;
    const int rA    = (aGp >> 2) | (aHalf << 1);
    // B loader: thread -> row n = tid&63, k-half = tid>>6
    const int bn    = tid & 63;
    const int bKb0  = (tid >> 6) << 1;     // kb base: 0 or 2
    const float* Wp = W + (size_t)(n0 + bn) * K + (bKb0 << 3);
    const int bJ    = bn >> 3;
    const int bGp   = bn & 7;
    const int rB    = (bGp >> 2) | ((bJ & 1) << 1);

    for (int k0 = 0; k0 < K; k0 += 32) {
        // ---- A tile -> fragment-order smem ----
        #pragma unroll
        for (int kb = 0; kb < 4; kb++) {
            float4 ve = *(const float4*)(Ap + k0 + kb * 8);
            float4 vo = *(const float4*)(Ap + k0 + kb * 8 + 4);
            float2 p[4], q[4];
            p[0] = make_float2(to_tf32(ve.x), to_tf32(vo.x));
            p[1] = make_float2(to_tf32(ve.y), to_tf32(vo.y));
            p[2] = make_float2(to_tf32(ve.z), to_tf32(vo.z));
            p[3] = make_float2(to_tf32(ve.w), to_tf32(vo.w));
            rot4(p, rA, q);
            float* base = As + (aGrp * 4 + kb) * 128 + aHalf * 64 + (aGp << 3);
            *(float2*)(base + ((0 ^ rA) << 1)) = q[0];
            *(float2*)(base + ((1 ^ rA) << 1)) = q[1];
            *(float2*)(base + ((2 ^ rA) << 1)) = q[2];
            *(float2*)(base + ((3 ^ rA) << 1)) = q[3];
        }
        // ---- B tile -> fragment-order smem ----
        #pragma unroll
        for (int kb2 = 0; kb2 < 2; kb2++) {
            float4 ve = *(const float4*)(Wp + k0 + kb2 * 8);
            float4 vo = *(const float4*)(Wp + k0 + kb2 * 8 + 4);
            float2 p[4], q[4];
            p[0] = make_float2(to_tf32(ve.x), to_tf32(vo.x));
            p[1] = make_float2(to_tf32(ve.y), to_tf32(vo.y));
            p[2] = make_float2(to_tf32(ve.z), to_tf32(vo.z));
            p[3] = make_float2(to_tf32(ve.w), to_tf32(vo.w));
            rot4(p, rB, q);
            float* base = Bs + (bJ * 4 + bKb0 + kb2) * 64 + (bGp << 3);
            *(float2*)(base + ((0 ^ rB) << 1)) = q[0];
            *(float2*)(base + ((1 ^ rB) << 1)) = q[1];
            *(float2*)(base + ((2 ^ rB) << 1)) = q[2];
            *(float2*)(base + ((3 ^ rB) << 1)) = q[3];
        }
        __syncthreads();

        #pragma unroll
        for (int kb = 0; kb < 4; kb++) {
            float af[4][4];
            #pragma unroll
            for (int i = 0; i < 4; i++) {
                const float* ca = As + (((wm >> 4) + i) * 4 + kb) * 128 + (gp << 3) + (tg << 1);
                float2 lo = *(const float2*)(ca);
                float2 hi = *(const float2*)(ca + 64);
                af[i][0] = lo.x; af[i][1] = hi.x; af[i][2] = lo.y; af[i][3] = hi.y;
            }
            float bf[4][2];
            #pragma unroll
            for (int j = 0; j < 4; j++) {
                const float* cb = Bs + (((wn >> 3) + j) * 4 + kb) * 64 + (gp << 3) + (tg << 1);
                float2 v = *(const float2*)(cb);
                bf[j][0] = v.x; bf[j][1] = v.y;
            }
            #pragma unroll
            for (int i = 0; i < 4; i++)
                #pragma unroll
                for (int j = 0; j < 4; j++)
                    mma_tf32(acc[i][j], af[i], bf[j]);
        }
        __syncthreads();
    }

    // epilogue (c-frag rows: gp, gp+8; cols tg*2, tg*2+1 per n8 block)
    #pragma unroll
    for (int i = 0; i < 4; i++) {
        #pragma unroll
        for (int half = 0; half < 2; half++) {
            const int row = m0 + wm + (i << 4) + gp + (half << 3);
            size_t rowoff;
            if (EPI == 2) {
                int wi2 = row / Nn, nn2 = row - wi2 * Nn;
                int bi = wi2 >> 6, wl = wi2 & 63;
                int wr = wl >> 3, wc = wl & 7;
                int rr = nn2 / 7, cc = nn2 - rr * 7;
                int hd = (wr * 7 + rr + SS) % Hh;
                int wd = (wc * 7 + cc + SS) % Ww;
                rowoff = ((size_t)bi * (Hh * Ww) + hd * Ww + wd) * (size_t)Nc;
            } else {
                rowoff = (size_t)row * Nc;
            }
            #pragma unroll
            for (int j = 0; j < 4; j++) {
                const int ncol = n0 + wn + (j << 3) + (tg << 1);
                #pragma unroll
                for (int e = 0; e < 2; e++) {
                    float cv = acc[i][j][half * 2 + e] + bias[ncol + e];
                    if (EPI == 1)
                        cv = 0.5f * cv * (1.0f + erff(cv * 0.70710678118654752f));
                    if (EPI == 2 || EPI == 3)
                        cv += resid[rowoff + ncol + e];
                    C[rowoff + ncol + e] = cv;
                }
            }
        }
    }
}

// ---------------- fused window attention: one block per (window, head) ----------------
__global__ void __launch_bounds__(256)
attn_k(const float* __restrict__ rpb) {
    __shared__ float sq[Nn][HD + 1];
    __shared__ float sk[Nn][HD + 1];
    __shared__ float sv[Nn][HD + 1];
    __shared__ float p[Nn][Nn];
    __shared__ int   rg[Nn];

    const int wi = blockIdx.x;
    const int nh = blockIdx.y;
    const int tid = threadIdx.x;

    for (int i = tid; i < Nn * HD; i += 256) {
        int n = i >> 5, d = i & 31;
        const float* base = g_qkv + (size_t)(wi * Nn + n) * (3 * Cc) + nh * HD + d;
        sq[n][d] = base[0];
        sk[n][d] = base[Cc];
        sv[n][d] = base[2 * Cc];
    }
    if (tid < Nn) {
        int wl = wi & 63;
        int wr = wl >> 3, wc = wl & 7;
        int r = tid / 7, c2 = tid - (tid / 7) * 7;
        int hs = wr * 7 + r, ws = wc * 7 + c2;
        int rh = hs < (Hh - WS) ? 0 : (hs < (Hh - SS) ? 1 : 2);
        int rw = ws < (Ww - WS) ? 0 : (ws < (Ww - SS) ? 1 : 2);
        rg[tid] = rh * 3 + rw;
    }
    __syncthreads();

    for (int i = tid; i < Nn * Nn; i += 256) {
        int n = i / Nn, m = i - n * Nn;
        float acc = 0.0f;
        #pragma unroll 8
        for (int d = 0; d < HD; d++) acc += sq[n][d] * sk[m][d];
        int r1 = n / 7, c1 = n - r1 * 7;
        int r2 = m / 7, c2 = m - r2 * 7;
        int idx = (r1 - r2 + 6) * 13 + (c1 - c2 + 6);
        float bias = rpb[idx * NHd + nh];
        float mask = (rg[n] == rg[m]) ? 0.0f : -100.0f;
        p[n][m] = acc * SCALE + bias + mask;
    }
    __syncthreads();

    int warp = tid >> 5, lane = tid & 31;
    for (int n = warp; n < Nn; n += 8) {
        float mx = -1e30f;
        for (int m = lane; m < Nn; m += 32) mx = fmaxf(mx, p[n][m]);
        #pragma unroll
        for (int o = 16; o; o >>= 1) mx = fmaxf(mx, __shfl_xor_sync(0xffffffffu, mx, o));
        float sm = 0.0f;
        for (int m = lane; m < Nn; m += 32) {
            float e = __expf(p[n][m] - mx);
            p[n][m] = e;
            sm += e;
        }
        #pragma unroll
        for (int o = 16; o; o >>= 1) sm += __shfl_xor_sync(0xffffffffu, sm, o);
        float inv = 1.0f / sm;
        for (int m = lane; m < Nn; m += 32) p[n][m] *= inv;
    }
    __syncthreads();

    for (int i = tid; i < Nn * HD; i += 256) {
        int n = i >> 5, d = i & 31;
        float acc = 0.0f;
        #pragma unroll 7
        for (int m = 0; m < Nn; m++) acc += p[n][m] * sv[m][d];
        g_attn[(size_t)(wi * Nn + n) * Cc + nh * HD + d] = acc;
    }
}

// ---------------- host ----------------
extern "C" void kernel_launch(void* const* d_in, const int* in_sizes, int n_in,
                              void* d_out, int out_size) {
    const float* x     = (const float*)d_in[0];
    const float* n1g   = (const float*)d_in[1];
    const float* n1b   = (const float*)d_in[2];
    const float* qkvw  = (const float*)d_in[3];
    const float* qkvb  = (const float*)d_in[4];
    const float* projw = (const float*)d_in[5];
    const float* projb = (const float*)d_in[6];
    const float* rpb   = (const float*)d_in[7];
    const float* n2g   = (const float*)d_in[8];
    const float* n2b   = (const float*)d_in[9];
    const float* fc1w  = (const float*)d_in[10];
    const float* fc1b  = (const float*)d_in[11];
    const float* fc2w  = (const float*)d_in[12];
    const float* fc2b  = (const float*)d_in[13];
    float* out = (float*)d_out;

    static float *p_xw = nullptr, *p_qkv = nullptr, *p_attn = nullptr,
                 *p_h = nullptr, *p_ln2 = nullptr, *p_act = nullptr;
    if (!p_xw) {
        cudaGetSymbolAddress((void**)&p_xw,  g_xw);
        cudaGetSymbolAddress((void**)&p_qkv, g_qkv);
        cudaGetSymbolAddress((void**)&p_attn,g_attn);
        cudaGetSymbolAddress((void**)&p_h,   g_h);
        cudaGetSymbolAddress((void**)&p_ln2, g_ln2);
        cudaGetSymbolAddress((void**)&p_act, g_act);
    }

    // 1) LN1 + roll + window partition
    ln1_shift_part<<<TOK, 192>>>(x, n1g, n1b);
    // 2) QKV GEMM  [TOK,576]
    gemm_tc<0><<<dim3((3 * Cc) / 64, TOK / 128), 128>>>(p_xw, qkvw, qkvb, nullptr, p_qkv, TOK, 3 * Cc, Cc);
    // 3) window attention
    attn_k<<<dim3(NWTOT, NHd), 256>>>(rpb);
    // 4) proj GEMM fused with window-reverse + roll-back + residual -> h (token order)
    gemm_tc<2><<<dim3(Cc / 64, TOK / 128), 128>>>(p_attn, projw, projb, x, p_h, TOK, Cc, Cc);
    // 5) LN2
    ln2_k<<<TOK, 192>>>(n2g, n2b);
    // 6) FC1 + GELU
    gemm_tc<1><<<dim3(HID / 64, TOK / 128), 128>>>(p_ln2, fc1w, fc1b, nullptr, p_act, TOK, HID, Cc);
    // 7) FC2 + residual -> out
    gemm_tc<3><<<dim3(Cc / 64, TOK / 128), 128>>>(p_act, fc2w, fc2b, p_h, out, TOK, Cc, HID);
}

// round 6
// speedup vs baseline: 2.4065x; 1.5426x over previous
#include <cuda_runtime.h>
#include <cuda_fp16.h>
#include <math.h>
#include <stddef.h>
#include <stdint.h>

#define Bb   32
#define Hh   56
#define Ww   56
#define Cc   192
#define WS   7
#define SS   3
#define NHd  6
#define Nn   49
#define HD   32
#define NWTOT 2048
#define TOK  100352
#define HID  768
#define SCALE 0.17677669529663687f  /* 32^-0.5 */

// ---------------- scratch (device globals; no allocations) ----------------
__device__ __half g_xw16  [(size_t)TOK * Cc];       // LN1+shift+partition (window order, fp16)
__device__ __half g_qkv16 [(size_t)TOK * 3 * Cc];   // qkv (window order, fp16)
__device__ __half g_attn16[(size_t)TOK * Cc];       // attention out (window order, fp16)
__device__ float  g_h     [(size_t)TOK * Cc];       // h = x + attn_proj (token order, fp32)
__device__ __half g_ln216 [(size_t)TOK * Cc];       // LN2(h) fp16
__device__ __half g_act16 [(size_t)TOK * HID];      // gelu(fc1) fp16
__device__ __half g_qkvw16[3 * Cc * Cc];
__device__ __half g_projw16[Cc * Cc];
__device__ __half g_fc1w16[HID * Cc];
__device__ __half g_fc2w16[Cc * HID];

// ---------------- helpers ----------------
static __device__ __forceinline__ uint32_t smem_u32(const void* p) {
    uint32_t a;
    asm("{ .reg .u64 t; cvta.to.shared.u64 t, %1; cvt.u32.u64 %0, t; }" : "=r"(a) : "l"(p));
    return a;
}
static __device__ __forceinline__ void ldsm4(uint32_t& r0, uint32_t& r1, uint32_t& r2,
                                             uint32_t& r3, uint32_t addr) {
    asm volatile("ldmatrix.sync.aligned.m8n8.x4.shared.b16 {%0,%1,%2,%3}, [%4];"
                 : "=r"(r0), "=r"(r1), "=r"(r2), "=r"(r3) : "r"(addr));
}
static __device__ __forceinline__ void mma_f16(float* c, const uint32_t* a, const uint32_t* b) {
    asm volatile(
        "mma.sync.aligned.m16n8k16.row.col.f32.f16.f16.f32 "
        "{%0,%1,%2,%3}, {%4,%5,%6,%7}, {%8,%9}, {%0,%1,%2,%3};"
        : "+f"(c[0]), "+f"(c[1]), "+f"(c[2]), "+f"(c[3])
        : "r"(a[0]), "r"(a[1]), "r"(a[2]), "r"(a[3]), "r"(b[0]), "r"(b[1]));
}

// ---------------- block reduce over 192 threads (6 warps) ----------------
__device__ __forceinline__ float blk_sum192(float v, float* red) {
    #pragma unroll
    for (int o = 16; o; o >>= 1) v += __shfl_xor_sync(0xffffffffu, v, o);
    if ((threadIdx.x & 31) == 0) red[threadIdx.x >> 5] = v;
    __syncthreads();
    float t = red[0] + red[1] + red[2] + red[3] + red[4] + red[5];
    __syncthreads();
    return t;
}

// ---------------- weight conversion ----------------
__global__ void cvt16(const float* __restrict__ s, __half* __restrict__ d, int n) {
    int i = blockIdx.x * 256 + threadIdx.x;
    if (i < n) d[i] = __float2half(s[i]);
}

// ---------------- LN1 + roll(-3,-3) + window partition -> fp16 ----------------
__global__ void ln1_shift_part(const float* __restrict__ x,
                               const float* __restrict__ g,
                               const float* __restrict__ b) {
    __shared__ float red[6];
    int t  = blockIdx.x;
    int wi = t / Nn, n = t - wi * Nn;
    int bi = wi >> 6, wl = wi & 63;
    int wr = wl >> 3, wc = wl & 7;
    int r  = n / 7,  c2 = n - r * 7;
    int hsrc = (wr * 7 + r + SS) % Hh;
    int wsrc = (wc * 7 + c2 + SS) % Ww;
    const float* row = x + ((size_t)bi * (Hh * Ww) + hsrc * Ww + wsrc) * Cc;
    int c = threadIdx.x;
    float v = row[c];
    float mean = blk_sum192(v, red) * (1.0f / Cc);
    float d = v - mean;
    float var = blk_sum192(d * d, red) * (1.0f / Cc);
    g_xw16[(size_t)t * Cc + c] = __float2half(d * rsqrtf(var + 1e-5f) * g[c] + b[c]);
}

// ---------------- LN2 (token order) -> fp16 ----------------
__global__ void ln2_k(const float* __restrict__ g, const float* __restrict__ b) {
    __shared__ float red[6];
    int t = blockIdx.x, c = threadIdx.x;
    float v = g_h[(size_t)t * Cc + c];
    float mean = blk_sum192(v, red) * (1.0f / Cc);
    float d = v - mean;
    float var = blk_sum192(d * d, red) * (1.0f / Cc);
    g_ln216[(size_t)t * Cc + c] = __float2half(d * rsqrtf(var + 1e-5f) * g[c] + b[c]);
}

// ---------------- fp16 tensor-core GEMM: C = A[M,K] @ W[Nc,K]^T + bias ----------------
// BM=128, BN=64, BK=32 (halfs); 128 threads (4 warps 2x2), warp tile 64x32.
// A,B fragments via ldmatrix.x4; fp32 accumulate.
// Smem rows padded to 40 halfs (80B) -> LDSM conflict-free (stride 80 distinct mod 128).
// EPI: 0 = +bias -> fp16 (qkv)   1 = +bias,GELU -> fp16 (fc1)
//      2 = +bias, scatter window->token, +resid -> fp32 (proj)
//      3 = +bias, +resid -> fp32 (fc2)
template <int EPI>
__global__ void __launch_bounds__(128)
gemm_f16(const __half* __restrict__ A, const __half* __restrict__ Wt,
         const float* __restrict__ bias, const float* __restrict__ resid,
         void* __restrict__ Cout, int Nc, int K) {
    __shared__ __half As[128 * 40];
    __shared__ __half Bs[64 * 40];

    const int tid  = threadIdx.x;
    const int wid  = tid >> 5, lane = tid & 31;
    const int gp   = lane >> 2, tg = lane & 3;
    const int m0   = blockIdx.y << 7;
    const int n0   = blockIdx.x << 6;
    const int wm   = (wid & 1) << 6;   // 0 / 64
    const int wn   = (wid >> 1) << 5;  // 0 / 32

    float acc[4][4][4];
    #pragma unroll
    for (int i = 0; i < 4; i++)
        #pragma unroll
        for (int j = 0; j < 4; j++)
            #pragma unroll
            for (int e = 0; e < 4; e++) acc[i][j][e] = 0.0f;

    // loader addresses
    const __half* Ap = A + (size_t)(m0 + tid) * K;           // one row per thread
    const int bRowL  = tid >> 1, bHalf = tid & 1;            // 2 threads per B row
    const __half* Wp = Wt + (size_t)(n0 + bRowL) * K + bHalf * 16;
    __half* AsW = As + tid * 40;
    __half* BsW = Bs + bRowL * 40 + bHalf * 16;

    // ldmatrix lane addressing
    const int aRow  = lane & 15;
    const int aCol8 = (lane >> 4) << 3;                       // 0 / 8
    const int bRow  = ((lane & 16) >> 1) + (lane & 7);        // tile-pair row
    const int bCol8 = lane & 8;                               // 0 / 8
    const uint32_t aBase = smem_u32(As) + (((wm + aRow) * 40 + aCol8) << 1);
    const uint32_t bBase = smem_u32(Bs) + (((wn + bRow) * 40 + bCol8) << 1);

    for (int k0 = 0; k0 < K; k0 += 32) {
        // A tile: 128 rows x 32 halfs
        {
            const uint4* src = (const uint4*)(Ap + k0);
            uint4* dst = (uint4*)AsW;
            dst[0] = src[0]; dst[1] = src[1]; dst[2] = src[2]; dst[3] = src[3];
        }
        // B tile: 64 rows x 32 halfs (2 threads/row)
        {
            const uint4* src = (const uint4*)(Wp + k0);
            uint4* dst = (uint4*)BsW;
            dst[0] = src[0]; dst[1] = src[1];
        }
        __syncthreads();

        #pragma unroll
        for (int kk = 0; kk < 2; kk++) {
            uint32_t af[4][4];
            #pragma unroll
            for (int i = 0; i < 4; i++)
                ldsm4(af[i][0], af[i][1], af[i][2], af[i][3],
                      aBase + ((i * 16 * 40 + kk * 16) << 1));
            uint32_t bf[4][2];
            ldsm4(bf[0][0], bf[0][1], bf[1][0], bf[1][1], bBase + ((kk * 16) << 1));
            ldsm4(bf[2][0], bf[2][1], bf[3][0], bf[3][1], bBase + ((16 * 40 + kk * 16) << 1));
            #pragma unroll
            for (int i = 0; i < 4; i++)
                #pragma unroll
                for (int j = 0; j < 4; j++)
                    mma_f16(acc[i][j], af[i], bf[j]);
        }
        __syncthreads();
    }

    // epilogue (c-frag rows: gp, gp+8; cols tg*2, tg*2+1 per n8 block)
    #pragma unroll
    for (int i = 0; i < 4; i++) {
        #pragma unroll
        for (int half = 0; half < 2; half++) {
            const int row = m0 + wm + (i << 4) + gp + (half << 3);
            size_t rowoff;
            if (EPI == 2) {
                int wi2 = row / Nn, nn2 = row - wi2 * Nn;
                int bi = wi2 >> 6, wl = wi2 & 63;
                int wr = wl >> 3, wc = wl & 7;
                int rr = nn2 / 7, cc = nn2 - rr * 7;
                int hd = (wr * 7 + rr + SS) % Hh;
                int wd = (wc * 7 + cc + SS) % Ww;
                rowoff = ((size_t)bi * (Hh * Ww) + hd * Ww + wd) * (size_t)Nc;
            } else {
                rowoff = (size_t)row * Nc;
            }
            #pragma unroll
            for (int j = 0; j < 4; j++) {
                const int ncol = n0 + wn + (j << 3) + (tg << 1);
                float v0 = acc[i][j][half * 2 + 0] + bias[ncol + 0];
                float v1 = acc[i][j][half * 2 + 1] + bias[ncol + 1];
                if (EPI == 1) {
                    v0 = 0.5f * v0 * (1.0f + erff(v0 * 0.70710678118654752f));
                    v1 = 0.5f * v1 * (1.0f + erff(v1 * 0.70710678118654752f));
                }
                if (EPI == 0 || EPI == 1) {
                    *(__half2*)((__half*)Cout + rowoff + ncol) = __floats2half2_rn(v0, v1);
                } else {
                    v0 += resid[rowoff + ncol + 0];
                    v1 += resid[rowoff + ncol + 1];
                    *(float2*)((float*)Cout + rowoff + ncol) = make_float2(v0, v1);
                }
            }
        }
    }
}

// ---------------- fused window attention (fp16 in/out, fp32 math) ----------------
__global__ void __launch_bounds__(256)
attn_k(const float* __restrict__ rpb) {
    __shared__ float sq[Nn][HD + 1];
    __shared__ float sk[Nn][HD + 1];
    __shared__ float sv[Nn][HD + 1];
    __shared__ float p[Nn][Nn];
    __shared__ int   rg[Nn];

    const int wi = blockIdx.x;
    const int nh = blockIdx.y;
    const int tid = threadIdx.x;

    for (int i = tid; i < Nn * HD; i += 256) {
        int n = i >> 5, d = i & 31;
        const __half* base = g_qkv16 + (size_t)(wi * Nn + n) * (3 * Cc) + nh * HD + d;
        sq[n][d] = __half2float(base[0]);
        sk[n][d] = __half2float(base[Cc]);
        sv[n][d] = __half2float(base[2 * Cc]);
    }
    if (tid < Nn) {
        int wl = wi & 63;
        int wr = wl >> 3, wc = wl & 7;
        int r = tid / 7, c2 = tid - (tid / 7) * 7;
        int hs = wr * 7 + r, ws = wc * 7 + c2;
        int rh = hs < (Hh - WS) ? 0 : (hs < (Hh - SS) ? 1 : 2);
        int rw = ws < (Ww - WS) ? 0 : (ws < (Ww - SS) ? 1 : 2);
        rg[tid] = rh * 3 + rw;
    }
    __syncthreads();

    for (int i = tid; i < Nn * Nn; i += 256) {
        int n = i / Nn, m = i - n * Nn;
        float acc = 0.0f;
        #pragma unroll 8
        for (int d = 0; d < HD; d++) acc += sq[n][d] * sk[m][d];
        int r1 = n / 7, c1 = n - r1 * 7;
        int r2 = m / 7, c2 = m - r2 * 7;
        int idx = (r1 - r2 + 6) * 13 + (c1 - c2 + 6);
        float bias = rpb[idx * NHd + nh];
        float mask = (rg[n] == rg[m]) ? 0.0f : -100.0f;
        p[n][m] = acc * SCALE + bias + mask;
    }
    __syncthreads();

    int warp = tid >> 5, lane = tid & 31;
    for (int n = warp; n < Nn; n += 8) {
        float mx = -1e30f;
        for (int m = lane; m < Nn; m += 32) mx = fmaxf(mx, p[n][m]);
        #pragma unroll
        for (int o = 16; o; o >>= 1) mx = fmaxf(mx, __shfl_xor_sync(0xffffffffu, mx, o));
        float sm = 0.0f;
        for (int m = lane; m < Nn; m += 32) {
            float e = __expf(p[n][m] - mx);
            p[n][m] = e;
            sm += e;
        }
        #pragma unroll
        for (int o = 16; o; o >>= 1) sm += __shfl_xor_sync(0xffffffffu, sm, o);
        float inv = 1.0f / sm;
        for (int m = lane; m < Nn; m += 32) p[n][m] *= inv;
    }
    __syncthreads();

    for (int i = tid; i < Nn * HD; i += 256) {
        int n = i >> 5, d = i & 31;
        float acc = 0.0f;
        #pragma unroll 7
        for (int m = 0; m < Nn; m++) acc += p[n][m] * sv[m][d];
        g_attn16[(size_t)(wi * Nn + n) * Cc + nh * HD + d] = __float2half(acc);
    }
}

// ---------------- host ----------------
extern "C" void kernel_launch(void* const* d_in, const int* in_sizes, int n_in,
                              void* d_out, int out_size) {
    const float* x     = (const float*)d_in[0];
    const float* n1g   = (const float*)d_in[1];
    const float* n1b   = (const float*)d_in[2];
    const float* qkvw  = (const float*)d_in[3];
    const float* qkvb  = (const float*)d_in[4];
    const float* projw = (const float*)d_in[5];
    const float* projb = (const float*)d_in[6];
    const float* rpb   = (const float*)d_in[7];
    const float* n2g   = (const float*)d_in[8];
    const float* n2b   = (const float*)d_in[9];
    const float* fc1w  = (const float*)d_in[10];
    const float* fc1b  = (const float*)d_in[11];
    const float* fc2w  = (const float*)d_in[12];
    const float* fc2b  = (const float*)d_in[13];
    float* out = (float*)d_out;

    static __half *p_xw16 = nullptr, *p_qkv16, *p_attn16, *p_ln216, *p_act16,
                  *p_qkvw16, *p_projw16, *p_fc1w16, *p_fc2w16;
    static float *p_h;
    if (!p_xw16) {
        cudaGetSymbolAddress((void**)&p_xw16,   g_xw16);
        cudaGetSymbolAddress((void**)&p_qkv16,  g_qkv16);
        cudaGetSymbolAddress((void**)&p_attn16, g_attn16);
        cudaGetSymbolAddress((void**)&p_h,      g_h);
        cudaGetSymbolAddress((void**)&p_ln216,  g_ln216);
        cudaGetSymbolAddress((void**)&p_act16,  g_act16);
        cudaGetSymbolAddress((void**)&p_qkvw16, g_qkvw16);
        cudaGetSymbolAddress((void**)&p_projw16,g_projw16);
        cudaGetSymbolAddress((void**)&p_fc1w16, g_fc1w16);
        cudaGetSymbolAddress((void**)&p_fc2w16, g_fc2w16);
    }

    // 0) weight conversion (tiny)
    cvt16<<<(3 * Cc * Cc + 255) / 256, 256>>>(qkvw, p_qkvw16, 3 * Cc * Cc);
    cvt16<<<(Cc * Cc + 255) / 256, 256>>>(projw, p_projw16, Cc * Cc);
    cvt16<<<(HID * Cc + 255) / 256, 256>>>(fc1w, p_fc1w16, HID * Cc);
    cvt16<<<(Cc * HID + 255) / 256, 256>>>(fc2w, p_fc2w16, Cc * HID);

    // 1) LN1 + roll + window partition -> fp16
    ln1_shift_part<<<TOK, 192>>>(x, n1g, n1b);
    // 2) QKV GEMM  [TOK,576]
    gemm_f16<0><<<dim3((3 * Cc) / 64, TOK / 128), 128>>>(p_xw16, p_qkvw16, qkvb, nullptr, p_qkv16, 3 * Cc, Cc);
    // 3) window attention
    attn_k<<<dim3(NWTOT, NHd), 256>>>(rpb);
    // 4) proj GEMM + window-reverse + roll-back + residual -> h (fp32, token order)
    gemm_f16<2><<<dim3(Cc / 64, TOK / 128), 128>>>(p_attn16, p_projw16, projb, x, p_h, Cc, Cc);
    // 5) LN2 -> fp16
    ln2_k<<<TOK, 192>>>(n2g, n2b);
    // 6) FC1 + GELU -> fp16
    gemm_f16<1><<<dim3(HID / 64, TOK / 128), 128>>>(p_ln216, p_fc1w16, fc1b, nullptr, p_act16, HID, Cc);
    // 7) FC2 + residual -> out (fp32)
    gemm_f16<3><<<dim3(Cc / 64, TOK / 128), 128>>>(p_act16, p_fc2w16, fc2b, p_h, out, Cc, HID);
}

// round 7
// speedup vs baseline: 4.1123x; 1.7088x over previous
#include <cuda_runtime.h>
#include <cuda_fp16.h>
#include <math.h>
#include <stddef.h>
#include <stdint.h>

#define Bb   32
#define Hh   56
#define Ww   56
#define Cc   192
#define WS   7
#define SS   3
#define NHd  6
#define Nn   49
#define HD   32
#define NWTOT 2048
#define TOK  100352
#define HID  768
#define SCALE 0.17677669529663687f  /* 32^-0.5 */

// ---------------- scratch (device globals; no allocations) ----------------
__device__ __half g_xw16  [(size_t)TOK * Cc];
__device__ __half g_qkv16 [(size_t)TOK * 3 * Cc];
__device__ __half g_attn16[(size_t)TOK * Cc];
__device__ float  g_h     [(size_t)TOK * Cc];
__device__ __half g_ln216 [(size_t)TOK * Cc];
__device__ __half g_act16 [(size_t)TOK * HID];
__device__ __half g_qkvw16[3 * Cc * Cc];
__device__ __half g_projw16[Cc * Cc];
__device__ __half g_fc1w16[HID * Cc];
__device__ __half g_fc2w16[Cc * HID];

// ---------------- helpers ----------------
static __device__ __forceinline__ uint32_t smem_u32(const void* p) {
    uint32_t a;
    asm("{ .reg .u64 t; cvta.to.shared.u64 t, %1; cvt.u32.u64 %0, t; }" : "=r"(a) : "l"(p));
    return a;
}
static __device__ __forceinline__ void ldsm4(uint32_t& r0, uint32_t& r1, uint32_t& r2,
                                             uint32_t& r3, uint32_t addr) {
    asm volatile("ldmatrix.sync.aligned.m8n8.x4.shared.b16 {%0,%1,%2,%3}, [%4];"
                 : "=r"(r0), "=r"(r1), "=r"(r2), "=r"(r3) : "r"(addr));
}
static __device__ __forceinline__ void mma_f16(float* c, const uint32_t* a, const uint32_t* b) {
    asm volatile(
        "mma.sync.aligned.m16n8k16.row.col.f32.f16.f16.f32 "
        "{%0,%1,%2,%3}, {%4,%5,%6,%7}, {%8,%9}, {%0,%1,%2,%3};"
        : "+f"(c[0]), "+f"(c[1]), "+f"(c[2]), "+f"(c[3])
        : "r"(a[0]), "r"(a[1]), "r"(a[2]), "r"(a[3]), "r"(b[0]), "r"(b[1]));
}
static __device__ __forceinline__ void cpa16(uint32_t dst, const void* src) {
    asm volatile("cp.async.ca.shared.global [%0], [%1], 16;" :: "r"(dst), "l"(src));
}
static __device__ __forceinline__ uint32_t h2u(float a, float b) {
    __half2 h = __floats2half2_rn(a, b);
    return *(uint32_t*)&h;
}
#define DIV7(u) (((u) * 9363) >> 16)

// ---------------- warp reduce ----------------
static __device__ __forceinline__ float wsum(float v) {
    #pragma unroll
    for (int o = 16; o; o >>= 1) v += __shfl_xor_sync(0xffffffffu, v, o);
    return v;
}

// ---------------- fused weight conversion ----------------
__global__ void cvt_all(const float* __restrict__ qkvw, const float* __restrict__ projw,
                        const float* __restrict__ fc1w, const float* __restrict__ fc2w) {
    int i = blockIdx.x * 256 + threadIdx.x;
    const int S0 = 3 * Cc * Cc, S1 = Cc * Cc, S2 = HID * Cc, S3 = Cc * HID;
    if (i < S0) { g_qkvw16[i] = __float2half(qkvw[i]); return; }
    i -= S0;
    if (i < S1) { g_projw16[i] = __float2half(projw[i]); return; }
    i -= S1;
    if (i < S2) { g_fc1w16[i] = __float2half(fc1w[i]); return; }
    i -= S2;
    if (i < S3) { g_fc2w16[i] = __float2half(fc2w[i]); }
}

// ---------------- LN1 + roll(-3,-3) + window partition (warp per token) ----------------
__global__ void __launch_bounds__(256)
ln1_shift_part(const float* __restrict__ x, const float* __restrict__ g,
               const float* __restrict__ b) {
    int t = blockIdx.x * 8 + (threadIdx.x >> 5);
    int lane = threadIdx.x & 31;
    int wi = t / Nn, n = t - wi * Nn;
    int bi = wi >> 6, wl = wi & 63;
    int wr = wl >> 3, wc = wl & 7;
    int r = DIV7(n), c2 = n - r * 7;
    int hsrc = (wr * 7 + r + SS) % Hh;
    int wsrc = (wc * 7 + c2 + SS) % Ww;
    const float* row = x + ((size_t)bi * (Hh * Ww) + hsrc * Ww + wsrc) * Cc;
    float v[6];
    float s = 0.0f;
    #pragma unroll
    for (int j = 0; j < 6; j++) { v[j] = row[lane + 32 * j]; s += v[j]; }
    float mean = wsum(s) * (1.0f / Cc);
    float q = 0.0f;
    #pragma unroll
    for (int j = 0; j < 6; j++) { v[j] -= mean; q += v[j] * v[j]; }
    float inv = rsqrtf(wsum(q) * (1.0f / Cc) + 1e-5f);
    __half* o = g_xw16 + (size_t)t * Cc;
    #pragma unroll
    for (int j = 0; j < 6; j++) {
        int c = lane + 32 * j;
        o[c] = __float2half(v[j] * inv * g[c] + b[c]);
    }
}

// ---------------- LN2 (warp per token) ----------------
__global__ void __launch_bounds__(256)
ln2_k(const float* __restrict__ g, const float* __restrict__ b) {
    int t = blockIdx.x * 8 + (threadIdx.x >> 5);
    int lane = threadIdx.x & 31;
    const float* row = g_h + (size_t)t * Cc;
    float v[6];
    float s = 0.0f;
    #pragma unroll
    for (int j = 0; j < 6; j++) { v[j] = row[lane + 32 * j]; s += v[j]; }
    float mean = wsum(s) * (1.0f / Cc);
    float q = 0.0f;
    #pragma unroll
    for (int j = 0; j < 6; j++) { v[j] -= mean; q += v[j] * v[j]; }
    float inv = rsqrtf(wsum(q) * (1.0f / Cc) + 1e-5f);
    __half* o = g_ln216 + (size_t)t * Cc;
    #pragma unroll
    for (int j = 0; j < 6; j++) {
        int c = lane + 32 * j;
        o[c] = __float2half(v[j] * inv * g[c] + b[c]);
    }
}

// ---------------- fp16 TC GEMM, cp.async double-buffered ----------------
// BM=128, BN=64, BK=32; 128 threads (4 warps 2x2), warp tile 64x32.
template <int EPI>
__global__ void __launch_bounds__(128)
gemm_f16(const __half* __restrict__ A, const __half* __restrict__ Wt,
         const float* __restrict__ bias, const float* __restrict__ resid,
         void* __restrict__ Cout, int Nc, int K) {
    __shared__ __half As[2][128 * 40];
    __shared__ __half Bs[2][64 * 40];

    const int tid  = threadIdx.x;
    const int wid  = tid >> 5, lane = tid & 31;
    const int gp   = lane >> 2, tg = lane & 3;
    const int m0   = blockIdx.y << 7;
    const int n0   = blockIdx.x << 6;
    const int wm   = (wid & 1) << 6;
    const int wn   = (wid >> 1) << 5;

    float acc[4][4][4];
    #pragma unroll
    for (int i = 0; i < 4; i++)
        #pragma unroll
        for (int j = 0; j < 4; j++)
            #pragma unroll
            for (int e = 0; e < 4; e++) acc[i][j][e] = 0.0f;

    const __half* Ap = A + (size_t)(m0 + tid) * K;
    const int bRowL  = tid >> 1, bHalf = tid & 1;
    const __half* Wp = Wt + (size_t)(n0 + bRowL) * K + bHalf * 16;

    const uint32_t sA = smem_u32(As), sB = smem_u32(Bs);
    const uint32_t aDst0 = sA + tid * 80;                       // bytes
    const uint32_t bDst0 = sB + (bRowL * 40 + bHalf * 16) * 2;

    const int aRow  = lane & 15;
    const int aCol8 = (lane >> 4) << 3;
    const int bRow  = ((lane & 16) >> 1) + (lane & 7);
    const int bCol8 = lane & 8;
    const uint32_t aOff = ((wm + aRow) * 40 + aCol8) << 1;
    const uint32_t bOff = ((wn + bRow) * 40 + bCol8) << 1;

    const int nc = K >> 5;

    // prefetch chunk 0
    {
        #pragma unroll
        for (int s = 0; s < 4; s++) cpa16(aDst0 + s * 16, Ap + s * 8);
        cpa16(bDst0, Wp);
        cpa16(bDst0 + 16, Wp + 8);
        asm volatile("cp.async.commit_group;" ::: "memory");
    }

    for (int c = 0; c < nc; c++) {
        const int buf = c & 1;
        if (c + 1 < nc) {
            const int nb = (c + 1) & 1;
            const uint32_t aD = aDst0 + nb * 128 * 80;
            const uint32_t bD = bDst0 + nb * 64 * 80;
            const __half* Ag = Ap + (c + 1) * 32;
            const __half* Wg = Wp + (c + 1) * 32;
            #pragma unroll
            for (int s = 0; s < 4; s++) cpa16(aD + s * 16, Ag + s * 8);
            cpa16(bD, Wg);
            cpa16(bD + 16, Wg + 8);
            asm volatile("cp.async.commit_group;" ::: "memory");
            asm volatile("cp.async.wait_group 1;" ::: "memory");
        } else {
            asm volatile("cp.async.wait_group 0;" ::: "memory");
        }
        __syncthreads();

        const uint32_t aBase = sA + buf * (128 * 80) + aOff;
        const uint32_t bBase = sB + buf * (64 * 80) + bOff;
        #pragma unroll
        for (int kk = 0; kk < 2; kk++) {
            uint32_t af[4][4];
            #pragma unroll
            for (int i = 0; i < 4; i++)
                ldsm4(af[i][0], af[i][1], af[i][2], af[i][3],
                      aBase + ((i * 16 * 40 + kk * 16) << 1));
            uint32_t bf[4][2];
            ldsm4(bf[0][0], bf[0][1], bf[1][0], bf[1][1], bBase + ((kk * 16) << 1));
            ldsm4(bf[2][0], bf[2][1], bf[3][0], bf[3][1], bBase + ((16 * 40 + kk * 16) << 1));
            #pragma unroll
            for (int i = 0; i < 4; i++)
                #pragma unroll
                for (int j = 0; j < 4; j++)
                    mma_f16(acc[i][j], af[i], bf[j]);
        }
        __syncthreads();
    }

    // epilogue
    #pragma unroll
    for (int i = 0; i < 4; i++) {
        #pragma unroll
        for (int half = 0; half < 2; half++) {
            const int row = m0 + wm + (i << 4) + gp + (half << 3);
            size_t rowoff;
            if (EPI == 2) {
                int wi2 = row / Nn, nn2 = row - wi2 * Nn;
                int bi = wi2 >> 6, wl = wi2 & 63;
                int wr = wl >> 3, wc = wl & 7;
                int rr = DIV7(nn2), cc = nn2 - rr * 7;
                int hd = (wr * 7 + rr + SS) % Hh;
                int wd = (wc * 7 + cc + SS) % Ww;
                rowoff = ((size_t)bi * (Hh * Ww) + hd * Ww + wd) * (size_t)Nc;
            } else {
                rowoff = (size_t)row * Nc;
            }
            #pragma unroll
            for (int j = 0; j < 4; j++) {
                const int ncol = n0 + wn + (j << 3) + (tg << 1);
                float v0 = acc[i][j][half * 2 + 0] + bias[ncol + 0];
                float v1 = acc[i][j][half * 2 + 1] + bias[ncol + 1];
                if (EPI == 1) {
                    v0 = 0.5f * v0 * (1.0f + erff(v0 * 0.70710678118654752f));
                    v1 = 0.5f * v1 * (1.0f + erff(v1 * 0.70710678118654752f));
                }
                if (EPI == 0 || EPI == 1) {
                    *(__half2*)((__half*)Cout + rowoff + ncol) = __floats2half2_rn(v0, v1);
                } else {
                    v0 += resid[rowoff + ncol + 0];
                    v1 += resid[rowoff + ncol + 1];
                    *(float2*)((float*)Cout + rowoff + ncol) = make_float2(v0, v1);
                }
            }
        }
    }
}

// ---------------- tensor-core window attention: block = (window, head), 128 thr ----------------
__global__ void __launch_bounds__(128)
attn_k(const float* __restrict__ rpb) {
    __shared__ __half Qs[64 * 40];
    __shared__ __half Ks[64 * 40];
    __shared__ __half Vt[32 * 72];          // transposed V: [hd][seq(pad 72)]
    __shared__ float  biasS[169];
    __shared__ int    rgx[Nn];

    const int wi = blockIdx.x;
    const int nh = blockIdx.y;
    const int tid = threadIdx.x;
    const int wid = tid >> 5, lane = tid & 31;
    const int gp = lane >> 2, tg = lane & 3;

    // ---- load Q, K (64 rows x 32 halfs; rows >=49 zero) ----
    for (int idx = tid; idx < 64 * 4; idx += 128) {
        int row = idx >> 2, seg = idx & 3;
        uint4 zq = make_uint4(0, 0, 0, 0), zk = zq;
        if (row < Nn) {
            const __half* base = g_qkv16 + (size_t)(wi * Nn + row) * (3 * Cc) + nh * HD + seg * 8;
            zq = *(const uint4*)(base);
            zk = *(const uint4*)(base + Cc);
        }
        *(uint4*)(Qs + row * 40 + seg * 8) = zq;
        *(uint4*)(Ks + row * 40 + seg * 8) = zk;
    }
    // ---- load V transposed: Vt[d][seq] ----
    for (int idx = tid; idx < 64 * 16; idx += 128) {
        int row = idx >> 4, p = idx & 15;       // seq row, half2-pair of hd
        __half2 v = __float2half2_rn(0.0f);
        if (row < Nn)
            v = *(const __half2*)(g_qkv16 + (size_t)(wi * Nn + row) * (3 * Cc) + 2 * Cc + nh * HD + 2 * p);
        Vt[(2 * p) * 72 + row]     = __low2half(v);
        Vt[(2 * p + 1) * 72 + row] = __high2half(v);
    }
    for (int i = tid; i < 169; i += 128) biasS[i] = rpb[i * NHd + nh];
    if (tid < Nn) {
        int wl = wi & 63;
        int wr = wl >> 3, wc = wl & 7;
        int r = DIV7(tid), c2 = tid - r * 7;
        int hs = wr * 7 + r, ws = wc * 7 + c2;
        int rh = hs < (Hh - WS) ? 0 : (hs < (Hh - SS) ? 1 : 2);
        int rw = ws < (Ww - WS) ? 0 : (ws < (Ww - SS) ? 1 : 2);
        rgx[tid] = rh * 3 + rw;
    }
    __syncthreads();

    // ---- S = Q K^T : warp strip rows wid*16..+16, full 64 cols ----
    float st[8][4];
    #pragma unroll
    for (int j = 0; j < 8; j++)
        #pragma unroll
        for (int e = 0; e < 4; e++) st[j][e] = 0.0f;

    const int aRow  = lane & 15;
    const int aCol8 = (lane >> 4) << 3;
    const int bRow  = ((lane & 16) >> 1) + (lane & 7);
    const int bCol8 = lane & 8;
    const uint32_t qBase = smem_u32(Qs) + (((wid * 16 + aRow) * 40 + aCol8) << 1);
    const uint32_t kBase = smem_u32(Ks) + ((bRow * 40 + bCol8) << 1);

    #pragma unroll
    for (int kk = 0; kk < 2; kk++) {
        uint32_t af[4];
        ldsm4(af[0], af[1], af[2], af[3], qBase + (kk * 16 << 1));
        #pragma unroll
        for (int j2 = 0; j2 < 4; j2++) {
            uint32_t bf[2][2];
            ldsm4(bf[0][0], bf[0][1], bf[1][0], bf[1][1],
                  kBase + ((j2 * 16 * 40 + kk * 16) << 1));
            mma_f16(st[2 * j2],     af, bf[0]);
            mma_f16(st[2 * j2 + 1], af, bf[1]);
        }
    }

    // ---- bias + mask + softmax (in fragments; rows gp / gp+8 of strip) ----
    const int rowL = wid * 16 + gp, rowH = rowL + 8;
    #pragma unroll
    for (int hrow = 0; hrow < 2; hrow++) {
        const int rI = hrow ? rowH : rowL;
        int r1 = 0, c1 = 0, rgn = 0;
        bool rOK = rI < Nn;
        if (rOK) { r1 = DIV7(rI); c1 = rI - r1 * 7; rgn = rgx[rI]; }
        // apply bias/mask
        #pragma unroll
        for (int j = 0; j < 8; j++) {
            #pragma unroll
            for (int e = 0; e < 2; e++) {
                const int m = j * 8 + tg * 2 + e;
                float v = st[j][hrow * 2 + e];
                if (m < Nn) {
                    if (rOK) {
                        int r2 = DIV7(m), c2 = m - r2 * 7;
                        float bs = biasS[(r1 - r2 + 6) * 13 + (c1 - c2 + 6)];
                        float mk = (rgn == rgx[m]) ? 0.0f : -100.0f;
                        v = v * SCALE + bs + mk;
                    }
                } else v = -1e30f;
                st[j][hrow * 2 + e] = v;
            }
        }
        // row max/sum across tg quad
        float mx = -1e30f;
        #pragma unroll
        for (int j = 0; j < 8; j++) {
            mx = fmaxf(mx, st[j][hrow * 2]);
            mx = fmaxf(mx, st[j][hrow * 2 + 1]);
        }
        mx = fmaxf(mx, __shfl_xor_sync(0xffffffffu, mx, 1));
        mx = fmaxf(mx, __shfl_xor_sync(0xffffffffu, mx, 2));
        float sm = 0.0f;
        #pragma unroll
        for (int j = 0; j < 8; j++) {
            #pragma unroll
            for (int e = 0; e < 2; e++) {
                float ev = __expf(st[j][hrow * 2 + e] - mx);
                st[j][hrow * 2 + e] = ev;
                sm += ev;
            }
        }
        sm += __shfl_xor_sync(0xffffffffu, sm, 1);
        sm += __shfl_xor_sync(0xffffffffu, sm, 2);
        float inv = 1.0f / sm;
        #pragma unroll
        for (int j = 0; j < 8; j++) {
            st[j][hrow * 2] *= inv;
            st[j][hrow * 2 + 1] *= inv;
        }
    }

    // ---- O = P V : P fragments reused as A operand; B from Vt ----
    float o[4][4];
    #pragma unroll
    for (int jt = 0; jt < 4; jt++)
        #pragma unroll
        for (int e = 0; e < 4; e++) o[jt][e] = 0.0f;

    const uint32_t vBase = smem_u32(Vt) + ((bRow * 72 + bCol8) << 1);
    #pragma unroll
    for (int kk = 0; kk < 4; kk++) {
        uint32_t a[4];
        a[0] = h2u(st[2 * kk][0],     st[2 * kk][1]);
        a[1] = h2u(st[2 * kk][2],     st[2 * kk][3]);
        a[2] = h2u(st[2 * kk + 1][0], st[2 * kk + 1][1]);
        a[3] = h2u(st[2 * kk + 1][2], st[2 * kk + 1][3]);
        #pragma unroll
        for (int jj2 = 0; jj2 < 2; jj2++) {
            uint32_t bf[2][2];
            ldsm4(bf[0][0], bf[0][1], bf[1][0], bf[1][1],
                  vBase + ((jj2 * 16 * 72 + kk * 16) << 1));
            mma_f16(o[2 * jj2],     a, bf[0]);
            mma_f16(o[2 * jj2 + 1], a, bf[1]);
        }
    }

    // ---- write O rows < 49 ----
    __half* outp = g_attn16 + (size_t)wi * Nn * Cc + nh * HD;
    #pragma unroll
    for (int hrow = 0; hrow < 2; hrow++) {
        const int rI = hrow ? rowH : rowL;
        if (rI < Nn) {
            __half* rp = outp + (size_t)rI * Cc;
            #pragma unroll
            for (int jt = 0; jt < 4; jt++)
                *(__half2*)(rp + jt * 8 + tg * 2) =
                    __floats2half2_rn(o[jt][hrow * 2], o[jt][hrow * 2 + 1]);
        }
    }
}

// ---------------- host ----------------
extern "C" void kernel_launch(void* const* d_in, const int* in_sizes, int n_in,
                              void* d_out, int out_size) {
    const float* x     = (const float*)d_in[0];
    const float* n1g   = (const float*)d_in[1];
    const float* n1b   = (const float*)d_in[2];
    const float* qkvw  = (const float*)d_in[3];
    const float* qkvb  = (const float*)d_in[4];
    const float* projw = (const float*)d_in[5];
    const float* projb = (const float*)d_in[6];
    const float* rpb   = (const float*)d_in[7];
    const float* n2g   = (const float*)d_in[8];
    const float* n2b   = (const float*)d_in[9];
    const float* fc1w  = (const float*)d_in[10];
    const float* fc1b  = (const float*)d_in[11];
    const float* fc2w  = (const float*)d_in[12];
    const float* fc2b  = (const float*)d_in[13];
    float* out = (float*)d_out;

    static __half *p_xw16 = nullptr, *p_qkv16, *p_attn16, *p_ln216, *p_act16,
                  *p_qkvw16, *p_projw16, *p_fc1w16, *p_fc2w16;
    static float *p_h;
    if (!p_xw16) {
        cudaGetSymbolAddress((void**)&p_xw16,   g_xw16);
        cudaGetSymbolAddress((void**)&p_qkv16,  g_qkv16);
        cudaGetSymbolAddress((void**)&p_attn16, g_attn16);
        cudaGetSymbolAddress((void**)&p_h,      g_h);
        cudaGetSymbolAddress((void**)&p_ln216,  g_ln216);
        cudaGetSymbolAddress((void**)&p_act16,  g_act16);
        cudaGetSymbolAddress((void**)&p_qkvw16, g_qkvw16);
        cudaGetSymbolAddress((void**)&p_projw16,g_projw16);
        cudaGetSymbolAddress((void**)&p_fc1w16, g_fc1w16);
        cudaGetSymbolAddress((void**)&p_fc2w16, g_fc2w16);
    }

    // 0) weight conversion (one launch)
    const int CV = 3 * Cc * Cc + Cc * Cc + HID * Cc + Cc * HID;
    cvt_all<<<(CV + 255) / 256, 256>>>(qkvw, projw, fc1w, fc2w);

    // 1) LN1 + roll + window partition -> fp16 (warp per token)
    ln1_shift_part<<<TOK / 8, 256>>>(x, n1g, n1b);
    // 2) QKV GEMM  [TOK,576]
    gemm_f16<0><<<dim3((3 * Cc) / 64, TOK / 128), 128>>>(p_xw16, p_qkvw16, qkvb, nullptr, p_qkv16, 3 * Cc, Cc);
    // 3) window attention (tensor cores)
    attn_k<<<dim3(NWTOT, NHd), 128>>>(rpb);
    // 4) proj GEMM + window-reverse + roll-back + residual -> h (fp32, token order)
    gemm_f16<2><<<dim3(Cc / 64, TOK / 128), 128>>>(p_attn16, p_projw16, projb, x, p_h, Cc, Cc);
    // 5) LN2 -> fp16
    ln2_k<<<TOK / 8, 256>>>(n2g, n2b);
    // 6) FC1 + GELU -> fp16
    gemm_f16<1><<<dim3(HID / 64, TOK / 128), 128>>>(p_ln216, p_fc1w16, fc1b, nullptr, p_act16, HID, Cc);
    // 7) FC2 + residual -> out (fp32)
    gemm_f16<3><<<dim3(Cc / 64, TOK / 128), 128>>>(p_act16, p_fc2w16, fc2b, p_h, out, Cc, HID);
}

// round 8
// speedup vs baseline: 4.2653x; 1.0372x over previous
#include <cuda_runtime.h>
#include <cuda_fp16.h>
#include <math.h>
#include <stddef.h>
#include <stdint.h>

#define Bb   32
#define Hh   56
#define Ww   56
#define Cc   192
#define WS   7
#define SS   3
#define NHd  6
#define Nn   49
#define HD   32
#define NWTOT 2048
#define TOK  100352
#define HID  768
#define SCALE 0.17677669529663687f  /* 32^-0.5 */

// ---------------- scratch (device globals; no allocations) ----------------
__device__ __half g_xw16  [(size_t)TOK * Cc];
__device__ __half g_qkv16 [(size_t)TOK * 3 * Cc];
__device__ __half g_attn16[(size_t)TOK * Cc];
__device__ float  g_h     [(size_t)TOK * Cc];
__device__ __half g_ln216 [(size_t)TOK * Cc];
__device__ __half g_act16 [(size_t)TOK * HID];
__device__ __half g_qkvw16[3 * Cc * Cc];
__device__ __half g_projw16[Cc * Cc];
__device__ __half g_fc1w16[HID * Cc];
__device__ __half g_fc2w16[Cc * HID];
__device__ float  g_tab   [24 * 64 * 64];     // (cls*6+nh) x 64 x 64 bias+mask

// ---------------- helpers ----------------
static __device__ __forceinline__ uint32_t smem_u32(const void* p) {
    uint32_t a;
    asm("{ .reg .u64 t; cvta.to.shared.u64 t, %1; cvt.u32.u64 %0, t; }" : "=r"(a) : "l"(p));
    return a;
}
static __device__ __forceinline__ void ldsm4(uint32_t& r0, uint32_t& r1, uint32_t& r2,
                                             uint32_t& r3, uint32_t addr) {
    asm volatile("ldmatrix.sync.aligned.m8n8.x4.shared.b16 {%0,%1,%2,%3}, [%4];"
                 : "=r"(r0), "=r"(r1), "=r"(r2), "=r"(r3) : "r"(addr));
}
static __device__ __forceinline__ void mma_f16(float* c, const uint32_t* a, const uint32_t* b) {
    asm volatile(
        "mma.sync.aligned.m16n8k16.row.col.f32.f16.f16.f32 "
        "{%0,%1,%2,%3}, {%4,%5,%6,%7}, {%8,%9}, {%0,%1,%2,%3};"
        : "+f"(c[0]), "+f"(c[1]), "+f"(c[2]), "+f"(c[3])
        : "r"(a[0]), "r"(a[1]), "r"(a[2]), "r"(a[3]), "r"(b[0]), "r"(b[1]));
}
static __device__ __forceinline__ void cpa16(uint32_t dst, const void* src) {
    asm volatile("cp.async.ca.shared.global [%0], [%1], 16;" :: "r"(dst), "l"(src));
}
static __device__ __forceinline__ uint32_t h2u(float a, float b) {
    __half2 h = __floats2half2_rn(a, b);
    return *(uint32_t*)&h;
}
#define DIV7(u) (((u) * 9363) >> 16)

static __device__ __forceinline__ float wsum(float v) {
    #pragma unroll
    for (int o = 16; o; o >>= 1) v += __shfl_xor_sync(0xffffffffu, v, o);
    return v;
}

// ---------------- fused weight conversion ----------------
__global__ void cvt_all(const float* __restrict__ qkvw, const float* __restrict__ projw,
                        const float* __restrict__ fc1w, const float* __restrict__ fc2w) {
    int i = blockIdx.x * 256 + threadIdx.x;
    const int S0 = 3 * Cc * Cc, S1 = Cc * Cc, S2 = HID * Cc, S3 = Cc * HID;
    if (i < S0) { g_qkvw16[i] = __float2half(qkvw[i]); return; }
    i -= S0;
    if (i < S1) { g_projw16[i] = __float2half(projw[i]); return; }
    i -= S1;
    if (i < S2) { g_fc1w16[i] = __float2half(fc1w[i]); return; }
    i -= S2;
    if (i < S3) { g_fc2w16[i] = __float2half(fc2w[i]); }
}

// ---------------- bias+mask tables: 4 window classes x 6 heads x 64x64 ----------------
__global__ void build_tab(const float* __restrict__ rpb) {
    int cls = blockIdx.x / NHd, nh = blockIdx.x - cls * NHd;
    int lastR = (cls >> 1) & 1, lastC = cls & 1;
    float* tp = g_tab + blockIdx.x * 4096;
    for (int idx = threadIdx.x; idx < 4096; idx += 256) {
        int rI = idx >> 6, m = idx & 63;
        float v;
        if (rI >= Nn) v = 0.0f;
        else if (m >= Nn) v = -1e30f;
        else {
            int r1 = DIV7(rI), c1 = rI - r1 * 7;
            int r2 = DIV7(m),  c2 = m  - r2 * 7;
            float bias = rpb[((r1 - r2 + 6) * 13 + (c1 - c2 + 6)) * NHd + nh];
            int rg1 = (lastR ? (r1 < 4 ? 1 : 2) : 0) * 3 + (lastC ? (c1 < 4 ? 1 : 2) : 0);
            int rg2 = (lastR ? (r2 < 4 ? 1 : 2) : 0) * 3 + (lastC ? (c2 < 4 ? 1 : 2) : 0);
            v = bias + ((rg1 == rg2) ? 0.0f : -100.0f);
        }
        tp[idx] = v;
    }
}

// ---------------- LN1 + roll(-3,-3) + window partition (warp per token) ----------------
__global__ void __launch_bounds__(256)
ln1_shift_part(const float* __restrict__ x, const float* __restrict__ g,
               const float* __restrict__ b) {
    int t = blockIdx.x * 8 + (threadIdx.x >> 5);
    int lane = threadIdx.x & 31;
    int wi = t / Nn, n = t - wi * Nn;
    int bi = wi >> 6, wl = wi & 63;
    int wr = wl >> 3, wc = wl & 7;
    int r = DIV7(n), c2 = n - r * 7;
    int hsrc = (wr * 7 + r + SS) % Hh;
    int wsrc = (wc * 7 + c2 + SS) % Ww;
    const float* row = x + ((size_t)bi * (Hh * Ww) + hsrc * Ww + wsrc) * Cc;
    float v[6];
    float s = 0.0f;
    #pragma unroll
    for (int j = 0; j < 6; j++) { v[j] = row[lane + 32 * j]; s += v[j]; }
    float mean = wsum(s) * (1.0f / Cc);
    float q = 0.0f;
    #pragma unroll
    for (int j = 0; j < 6; j++) { v[j] -= mean; q += v[j] * v[j]; }
    float inv = rsqrtf(wsum(q) * (1.0f / Cc) + 1e-5f);
    __half* o = g_xw16 + (size_t)t * Cc;
    #pragma unroll
    for (int j = 0; j < 6; j++) {
        int c = lane + 32 * j;
        o[c] = __float2half(v[j] * inv * g[c] + b[c]);
    }
}

// ---------------- LN2 (warp per token) ----------------
__global__ void __launch_bounds__(256)
ln2_k(const float* __restrict__ g, const float* __restrict__ b) {
    int t = blockIdx.x * 8 + (threadIdx.x >> 5);
    int lane = threadIdx.x & 31;
    const float* row = g_h + (size_t)t * Cc;
    float v[6];
    float s = 0.0f;
    #pragma unroll
    for (int j = 0; j < 6; j++) { v[j] = row[lane + 32 * j]; s += v[j]; }
    float mean = wsum(s) * (1.0f / Cc);
    float q = 0.0f;
    #pragma unroll
    for (int j = 0; j < 6; j++) { v[j] -= mean; q += v[j] * v[j]; }
    float inv = rsqrtf(wsum(q) * (1.0f / Cc) + 1e-5f);
    __half* o = g_ln216 + (size_t)t * Cc;
    #pragma unroll
    for (int j = 0; j < 6; j++) {
        int c = lane + 32 * j;
        o[c] = __float2half(v[j] * inv * g[c] + b[c]);
    }
}

// ---------------- fp16 TC GEMM: BM=256, BN=64, BK=32; 256 thr (8 warps 4x2) ----------------
// EPI: 0 = +bias, Q-cols(<192) scaled by SCALE -> fp16 (qkv)
//      1 = +bias, GELU -> fp16 (fc1)
//      2 = +bias, scatter window->token, +resid -> fp32 (proj)
//      3 = +bias, +resid -> fp32 (fc2)
template <int EPI>
__global__ void __launch_bounds__(256)
gemm_f16(const __half* __restrict__ A, const __half* __restrict__ Wt,
         const float* __restrict__ bias, const float* __restrict__ resid,
         void* __restrict__ Cout, int Nc, int K) {
    __shared__ __half As[2][256 * 40];
    __shared__ __half Bs[2][64 * 40];

    const int tid  = threadIdx.x;
    const int wid  = tid >> 5, lane = tid & 31;
    const int gp   = lane >> 2, tg = lane & 3;
    const int m0   = blockIdx.y << 8;
    const int n0   = blockIdx.x << 6;
    const int wm   = (wid & 3) << 6;    // 0/64/128/192
    const int wn   = (wid >> 2) << 5;   // 0/32

    float acc[4][4][4];
    #pragma unroll
    for (int i = 0; i < 4; i++)
        #pragma unroll
        for (int j = 0; j < 4; j++)
            #pragma unroll
            for (int e = 0; e < 4; e++) acc[i][j][e] = 0.0f;

    const __half* Ap = A + (size_t)(m0 + tid) * K;         // one row per thread
    const int bRowL  = tid >> 2, bQ = tid & 3;             // 4 threads per B row
    const __half* Wp = Wt + (size_t)(n0 + bRowL) * K + bQ * 8;

    const uint32_t sA = smem_u32(As), sB = smem_u32(Bs);
    const uint32_t aDst0 = sA + tid * 80;
    const uint32_t bDst0 = sB + (bRowL * 40 + bQ * 8) * 2;

    const int aRow  = lane & 15;
    const int aCol8 = (lane >> 4) << 3;
    const int bRow  = ((lane & 16) >> 1) + (lane & 7);
    const int bCol8 = lane & 8;
    const uint32_t aOff = ((wm + aRow) * 40 + aCol8) << 1;
    const uint32_t bOff = ((wn + bRow) * 40 + bCol8) << 1;

    const int nc = K >> 5;

    // prefetch chunk 0
    #pragma unroll
    for (int s = 0; s < 4; s++) cpa16(aDst0 + s * 16, Ap + s * 8);
    cpa16(bDst0, Wp);
    asm volatile("cp.async.commit_group;" ::: "memory");

    for (int c = 0; c < nc; c++) {
        const int buf = c & 1;
        if (c + 1 < nc) {
            const int nb = (c + 1) & 1;
            const uint32_t aD = aDst0 + nb * (256 * 80);
            const uint32_t bD = bDst0 + nb * (64 * 80);
            const __half* Ag = Ap + (c + 1) * 32;
            const __half* Wg = Wp + (c + 1) * 32;
            #pragma unroll
            for (int s = 0; s < 4; s++) cpa16(aD + s * 16, Ag + s * 8);
            cpa16(bD, Wg);
            asm volatile("cp.async.commit_group;" ::: "memory");
            asm volatile("cp.async.wait_group 1;" ::: "memory");
        } else {
            asm volatile("cp.async.wait_group 0;" ::: "memory");
        }
        __syncthreads();

        const uint32_t aBase = sA + buf * (256 * 80) + aOff;
        const uint32_t bBase = sB + buf * (64 * 80) + bOff;
        #pragma unroll
        for (int kk = 0; kk < 2; kk++) {
            uint32_t af[4][4];
            #pragma unroll
            for (int i = 0; i < 4; i++)
                ldsm4(af[i][0], af[i][1], af[i][2], af[i][3],
                      aBase + ((i * 16 * 40 + kk * 16) << 1));
            uint32_t bf[4][2];
            ldsm4(bf[0][0], bf[0][1], bf[1][0], bf[1][1], bBase + ((kk * 16) << 1));
            ldsm4(bf[2][0], bf[2][1], bf[3][0], bf[3][1], bBase + ((16 * 40 + kk * 16) << 1));
            #pragma unroll
            for (int i = 0; i < 4; i++)
                #pragma unroll
                for (int j = 0; j < 4; j++)
                    mma_f16(acc[i][j], af[i], bf[j]);
        }
        __syncthreads();
    }

    // epilogue
    #pragma unroll
    for (int i = 0; i < 4; i++) {
        #pragma unroll
        for (int half = 0; half < 2; half++) {
            const int row = m0 + wm + (i << 4) + gp + (half << 3);
            size_t rowoff;
            if (EPI == 2) {
                int wi2 = row / Nn, nn2 = row - wi2 * Nn;
                int bi = wi2 >> 6, wl = wi2 & 63;
                int wr = wl >> 3, wc = wl & 7;
                int rr = DIV7(nn2), cc = nn2 - rr * 7;
                int hd = (wr * 7 + rr + SS) % Hh;
                int wd = (wc * 7 + cc + SS) % Ww;
                rowoff = ((size_t)bi * (Hh * Ww) + hd * Ww + wd) * (size_t)Nc;
            } else {
                rowoff = (size_t)row * Nc;
            }
            #pragma unroll
            for (int j = 0; j < 4; j++) {
                const int ncol = n0 + wn + (j << 3) + (tg << 1);
                float v0 = acc[i][j][half * 2 + 0] + bias[ncol + 0];
                float v1 = acc[i][j][half * 2 + 1] + bias[ncol + 1];
                if (EPI == 0 && ncol < Cc) { v0 *= SCALE; v1 *= SCALE; }
                if (EPI == 1) {
                    v0 = 0.5f * v0 * (1.0f + erff(v0 * 0.70710678118654752f));
                    v1 = 0.5f * v1 * (1.0f + erff(v1 * 0.70710678118654752f));
                }
                if (EPI == 0 || EPI == 1) {
                    *(__half2*)((__half*)Cout + rowoff + ncol) = __floats2half2_rn(v0, v1);
                } else {
                    v0 += resid[rowoff + ncol + 0];
                    v1 += resid[rowoff + ncol + 1];
                    *(float2*)((float*)Cout + rowoff + ncol) = make_float2(v0, v1);
                }
            }
        }
    }
}

// ---------------- tensor-core window attention: block = (window, head), 128 thr ----------------
// S accumulators initialized from precomputed bias+mask table; Q prescaled by SCALE.
__global__ void __launch_bounds__(128)
attn_k() {
    __shared__ __half Qs[64 * 40];
    __shared__ __half Ks[64 * 40];
    __shared__ __half Vt[32 * 72];

    const int wi = blockIdx.x;
    const int nh = blockIdx.y;
    const int tid = threadIdx.x;
    const int wid = tid >> 5, lane = tid & 31;
    const int gp = lane >> 2, tg = lane & 3;

    // window class: last window-row? last window-col?
    const int wl = wi & 63;
    const int cls = (((wl >> 3) == 7) ? 2 : 0) | (((wl & 7) == 7) ? 1 : 0);
    const float* tp = g_tab + (cls * NHd + nh) * 4096;

    // ---- load Q, K ----
    for (int idx = tid; idx < 64 * 4; idx += 128) {
        int row = idx >> 2, seg = idx & 3;
        uint4 zq = make_uint4(0, 0, 0, 0), zk = zq;
        if (row < Nn) {
            const __half* base = g_qkv16 + (size_t)(wi * Nn + row) * (3 * Cc) + nh * HD + seg * 8;
            zq = *(const uint4*)(base);
            zk = *(const uint4*)(base + Cc);
        }
        *(uint4*)(Qs + row * 40 + seg * 8) = zq;
        *(uint4*)(Ks + row * 40 + seg * 8) = zk;
    }
    // ---- load V transposed ----
    for (int idx = tid; idx < 64 * 16; idx += 128) {
        int row = idx >> 4, p = idx & 15;
        __half2 v = __float2half2_rn(0.0f);
        if (row < Nn)
            v = *(const __half2*)(g_qkv16 + (size_t)(wi * Nn + row) * (3 * Cc) + 2 * Cc + nh * HD + 2 * p);
        Vt[(2 * p) * 72 + row]     = __low2half(v);
        Vt[(2 * p + 1) * 72 + row] = __high2half(v);
    }

    // ---- init S fragments from table ----
    const int rowL = wid * 16 + gp, rowH = rowL + 8;
    float st[8][4];
    #pragma unroll
    for (int j = 0; j < 8; j++) {
        float2 vL = *(const float2*)(tp + rowL * 64 + j * 8 + tg * 2);
        float2 vH = *(const float2*)(tp + rowH * 64 + j * 8 + tg * 2);
        st[j][0] = vL.x; st[j][1] = vL.y;
        st[j][2] = vH.x; st[j][3] = vH.y;
    }
    __syncthreads();

    // ---- S += Q' K^T ----
    const int aRow  = lane & 15;
    const int aCol8 = (lane >> 4) << 3;
    const int bRow  = ((lane & 16) >> 1) + (lane & 7);
    const int bCol8 = lane & 8;
    const uint32_t qBase = smem_u32(Qs) + (((wid * 16 + aRow) * 40 + aCol8) << 1);
    const uint32_t kBase = smem_u32(Ks) + ((bRow * 40 + bCol8) << 1);

    #pragma unroll
    for (int kk = 0; kk < 2; kk++) {
        uint32_t af[4];
        ldsm4(af[0], af[1], af[2], af[3], qBase + (kk * 16 << 1));
        #pragma unroll
        for (int j2 = 0; j2 < 4; j2++) {
            uint32_t bf[2][2];
            ldsm4(bf[0][0], bf[0][1], bf[1][0], bf[1][1],
                  kBase + ((j2 * 16 * 40 + kk * 16) << 1));
            mma_f16(st[2 * j2],     af, bf[0]);
            mma_f16(st[2 * j2 + 1], af, bf[1]);
        }
    }

    // ---- softmax across tg quad ----
    #pragma unroll
    for (int hrow = 0; hrow < 2; hrow++) {
        float mx = -1e30f;
        #pragma unroll
        for (int j = 0; j < 8; j++) {
            mx = fmaxf(mx, st[j][hrow * 2]);
            mx = fmaxf(mx, st[j][hrow * 2 + 1]);
        }
        mx = fmaxf(mx, __shfl_xor_sync(0xffffffffu, mx, 1));
        mx = fmaxf(mx, __shfl_xor_sync(0xffffffffu, mx, 2));
        float sm = 0.0f;
        #pragma unroll
        for (int j = 0; j < 8; j++) {
            #pragma unroll
            for (int e = 0; e < 2; e++) {
                float ev = __expf(st[j][hrow * 2 + e] - mx);
                st[j][hrow * 2 + e] = ev;
                sm += ev;
            }
        }
        sm += __shfl_xor_sync(0xffffffffu, sm, 1);
        sm += __shfl_xor_sync(0xffffffffu, sm, 2);
        float inv = 1.0f / sm;
        #pragma unroll
        for (int j = 0; j < 8; j++) {
            st[j][hrow * 2] *= inv;
            st[j][hrow * 2 + 1] *= inv;
        }
    }

    // ---- O = P V ----
    float o[4][4];
    #pragma unroll
    for (int jt = 0; jt < 4; jt++)
        #pragma unroll
        for (int e = 0; e < 4; e++) o[jt][e] = 0.0f;

    const uint32_t vBase = smem_u32(Vt) + ((bRow * 72 + bCol8) << 1);
    #pragma unroll
    for (int kk = 0; kk < 4; kk++) {
        uint32_t a[4];
        a[0] = h2u(st[2 * kk][0],     st[2 * kk][1]);
        a[1] = h2u(st[2 * kk][2],     st[2 * kk][3]);
        a[2] = h2u(st[2 * kk + 1][0], st[2 * kk + 1][1]);
        a[3] = h2u(st[2 * kk + 1][2], st[2 * kk + 1][3]);
        #pragma unroll
        for (int jj2 = 0; jj2 < 2; jj2++) {
            uint32_t bf[2][2];
            ldsm4(bf[0][0], bf[0][1], bf[1][0], bf[1][1],
                  vBase + ((jj2 * 16 * 72 + kk * 16) << 1));
            mma_f16(o[2 * jj2],     a, bf[0]);
            mma_f16(o[2 * jj2 + 1], a, bf[1]);
        }
    }

    // ---- write O rows < 49 ----
    __half* outp = g_attn16 + (size_t)wi * Nn * Cc + nh * HD;
    #pragma unroll
    for (int hrow = 0; hrow < 2; hrow++) {
        const int rI = hrow ? rowH : rowL;
        if (rI < Nn) {
            __half* rp = outp + (size_t)rI * Cc;
            #pragma unroll
            for (int jt = 0; jt < 4; jt++)
                *(__half2*)(rp + jt * 8 + tg * 2) =
                    __floats2half2_rn(o[jt][hrow * 2], o[jt][hrow * 2 + 1]);
        }
    }
}

// ---------------- host ----------------
extern "C" void kernel_launch(void* const* d_in, const int* in_sizes, int n_in,
                              void* d_out, int out_size) {
    const float* x     = (const float*)d_in[0];
    const float* n1g   = (const float*)d_in[1];
    const float* n1b   = (const float*)d_in[2];
    const float* qkvw  = (const float*)d_in[3];
    const float* qkvb  = (const float*)d_in[4];
    const float* projw = (const float*)d_in[5];
    const float* projb = (const float*)d_in[6];
    const float* rpb   = (const float*)d_in[7];
    const float* n2g   = (const float*)d_in[8];
    const float* n2b   = (const float*)d_in[9];
    const float* fc1w  = (const float*)d_in[10];
    const float* fc1b  = (const float*)d_in[11];
    const float* fc2w  = (const float*)d_in[12];
    const float* fc2b  = (const float*)d_in[13];
    float* out = (float*)d_out;

    static __half *p_xw16 = nullptr, *p_qkv16, *p_attn16, *p_ln216, *p_act16,
                  *p_qkvw16, *p_projw16, *p_fc1w16, *p_fc2w16;
    static float *p_h;
    if (!p_xw16) {
        cudaGetSymbolAddress((void**)&p_xw16,   g_xw16);
        cudaGetSymbolAddress((void**)&p_qkv16,  g_qkv16);
        cudaGetSymbolAddress((void**)&p_attn16, g_attn16);
        cudaGetSymbolAddress((void**)&p_h,      g_h);
        cudaGetSymbolAddress((void**)&p_ln216,  g_ln216);
        cudaGetSymbolAddress((void**)&p_act16,  g_act16);
        cudaGetSymbolAddress((void**)&p_qkvw16, g_qkvw16);
        cudaGetSymbolAddress((void**)&p_projw16,g_projw16);
        cudaGetSymbolAddress((void**)&p_fc1w16, g_fc1w16);
        cudaGetSymbolAddress((void**)&p_fc2w16, g_fc2w16);
    }

    // 0) weight conversion + bias/mask tables
    const int CV = 3 * Cc * Cc + Cc * Cc + HID * Cc + Cc * HID;
    cvt_all<<<(CV + 255) / 256, 256>>>(qkvw, projw, fc1w, fc2w);
    build_tab<<<24, 256>>>(rpb);

    // 1) LN1 + roll + window partition -> fp16
    ln1_shift_part<<<TOK / 8, 256>>>(x, n1g, n1b);
    // 2) QKV GEMM (Q prescaled by SCALE in epilogue)
    gemm_f16<0><<<dim3((3 * Cc) / 64, TOK / 256), 256>>>(p_xw16, p_qkvw16, qkvb, nullptr, p_qkv16, 3 * Cc, Cc);
    // 3) window attention
    attn_k<<<dim3(NWTOT, NHd), 128>>>();
    // 4) proj GEMM + window-reverse + roll-back + residual -> h
    gemm_f16<2><<<dim3(Cc / 64, TOK / 256), 256>>>(p_attn16, p_projw16, projb, x, p_h, Cc, Cc);
    // 5) LN2 -> fp16
    ln2_k<<<TOK / 8, 256>>>(n2g, n2b);
    // 6) FC1 + GELU -> fp16
    gemm_f16<1><<<dim3(HID / 64, TOK / 256), 256>>>(p_ln216, p_fc1w16, fc1b, nullptr, p_act16, HID, Cc);
    // 7) FC2 + residual -> out
    gemm_f16<3><<<dim3(Cc / 64, TOK / 256), 256>>>(p_act16, p_fc2w16, fc2b, p_h, out, Cc, HID);
}